// round 10
// baseline (speedup 1.0000x reference)
#include <cuda_runtime.h>
#include <cuda_bf16.h>
#include <cstdint>
#include <math.h>

// ================= scratch =================
__device__ __nv_bfloat16 g_att_hi[4096 * 2048];
__device__ __nv_bfloat16 g_att_lo[4096 * 2048];
__device__ __nv_bfloat16 g_WoT_hi[2048 * 2048];
__device__ __nv_bfloat16 g_WoT_lo[2048 * 2048];
__device__ __nv_bfloat16 g_qh[4096 * 2048];
__device__ __nv_bfloat16 g_ql[4096 * 2048];
__device__ __nv_bfloat16 g_kh[4096 * 2048];
__device__ __nv_bfloat16 g_kl[4096 * 2048];
__device__ __nv_bfloat16 g_vth[4096 * 2048];
__device__ __nv_bfloat16 g_vtl[4096 * 2048];
__device__ float2 g_rope[2048 * 64];
// int8 16-bit fixed-point operands for the QKV GEMM
__device__ signed char g_xq_h[4096 * 2048];
__device__ signed char g_xq_l[4096 * 2048];
__device__ signed char g_wq_h[6144 * 2048];   // WqkvT [n][k]
__device__ signed char g_wq_l[6144 * 2048];
__device__ unsigned g_maxx_bits;   // |x| max as float bits (atomicMax-idempotent)
__device__ unsigned g_maxw_bits;

// ================= helpers =================
__device__ __forceinline__ uint32_t smem_u32(const void* p) {
    uint32_t a;
    asm("{ .reg .u64 t; cvta.to.shared.u64 t, %1; cvt.u32.u64 %0, t; }" : "=r"(a) : "l"(p));
    return a;
}
__device__ __forceinline__ void ldsm4(uint32_t (&r)[4], uint32_t addr) {
    asm volatile("ldmatrix.sync.aligned.m8n8.x4.shared.b16 {%0,%1,%2,%3}, [%4];"
        : "=r"(r[0]), "=r"(r[1]), "=r"(r[2]), "=r"(r[3]) : "r"(addr));
}
__device__ __forceinline__ void mma16816(float* c, const uint32_t* a, const uint32_t* b) {
    asm volatile("mma.sync.aligned.m16n8k16.row.col.f32.bf16.bf16.f32 "
        "{%0,%1,%2,%3}, {%4,%5,%6,%7}, {%8,%9}, {%0,%1,%2,%3};"
        : "+f"(c[0]), "+f"(c[1]), "+f"(c[2]), "+f"(c[3])
        : "r"(a[0]), "r"(a[1]), "r"(a[2]), "r"(a[3]), "r"(b[0]), "r"(b[1]));
}
__device__ __forceinline__ void imma16832(int* c, const uint32_t* a, const uint32_t* b) {
    asm volatile("mma.sync.aligned.m16n8k32.row.col.s32.s8.s8.s32 "
        "{%0,%1,%2,%3}, {%4,%5,%6,%7}, {%8,%9}, {%0,%1,%2,%3};"
        : "+r"(c[0]), "+r"(c[1]), "+r"(c[2]), "+r"(c[3])
        : "r"(a[0]), "r"(a[1]), "r"(a[2]), "r"(a[3]), "r"(b[0]), "r"(b[1]));
}
__device__ __forceinline__ void cp16(uint32_t sa, const void* g) {
    asm volatile("cp.async.cg.shared.global [%0], [%1], 16;" :: "r"(sa), "l"(g));
}
#define CP_COMMIT() asm volatile("cp.async.commit_group;" ::: "memory")
#define CP_WAIT0()  asm volatile("cp.async.wait_group 0;" ::: "memory")
#define CP_WAIT1()  asm volatile("cp.async.wait_group 1;" ::: "memory")
__device__ __forceinline__ uint32_t bf2_bits(__nv_bfloat162 v) {
    return *reinterpret_cast<uint32_t*>(&v);
}
__device__ __forceinline__ void stage_split(__nv_bfloat16* hi, __nv_bfloat16* lo,
                                            int off, float v) {
    __nv_bfloat16 h = __float2bfloat16(v);
    hi[off] = h;
    lo[off] = __float2bfloat16(v - __bfloat162float(h));
}

// ================= prep kernels =================
__global__ void rope_table_kernel()
{
    const int idx = blockIdx.x * blockDim.x + threadIdx.x;
    const int j = idx & 63;
    const int s = idx >> 6;
    const float theta = 1.0f / powf(10000.0f, (float)(2 * j) / 128.0f);
    float sn, cs;
    sincosf((float)s * theta, &sn, &cs);
    g_rope[idx] = make_float2(cs, sn);
}

__global__ void maxabs_kernel(const float* __restrict__ p, int n, unsigned* out)
{
    float m = 0.0f;
    for (int i = blockIdx.x * blockDim.x + threadIdx.x; i < n; i += gridDim.x * blockDim.x)
        m = fmaxf(m, fabsf(p[i]));
#pragma unroll
    for (int s = 16; s > 0; s >>= 1)
        m = fmaxf(m, __shfl_xor_sync(0xffffffff, m, s));
    if ((threadIdx.x & 31) == 0)
        atomicMax(out, __float_as_uint(m));
}

__global__ void quant_x_kernel(const float* __restrict__ x, int n)
{
    const int i = blockIdx.x * blockDim.x + threadIdx.x;
    if (i >= n) return;
    const float inv = 32256.0f / __uint_as_float(g_maxx_bits);
    const int q = __float2int_rn(x[i] * inv);
    const int a = (q + 128) >> 8;
    g_xq_h[i] = (signed char)a;
    g_xq_l[i] = (signed char)(q - (a << 8));
}

// W[K,N] -> quantized WT[N,K] int8 hi/lo
__global__ void quantT_w_kernel(const float* __restrict__ W, int K, int N)
{
    __shared__ float s[32][33];
    int n0 = blockIdx.x * 32, k0 = blockIdx.y * 32;
    int tx = threadIdx.x, ty = threadIdx.y;
#pragma unroll
    for (int j = 0; j < 32; j += 8)
        s[ty + j][tx] = W[(size_t)(k0 + ty + j) * N + n0 + tx];
    __syncthreads();
    const float inv = 32256.0f / __uint_as_float(g_maxw_bits);
#pragma unroll
    for (int j = 0; j < 32; j += 8) {
        const int q = __float2int_rn(s[tx][ty + j] * inv);
        const int a = (q + 128) >> 8;
        size_t o = (size_t)(n0 + ty + j) * K + k0 + tx;
        g_wq_h[o] = (signed char)a;
        g_wq_l[o] = (signed char)(q - (a << 8));
    }
}

// W[K,N] -> WT[N,K] bf16 hi/lo (Wo path, unchanged)
__global__ void transpose_split(const float* __restrict__ W,
                                __nv_bfloat16* __restrict__ Thi, __nv_bfloat16* __restrict__ Tlo,
                                int K, int N) {
    __shared__ float s[32][33];
    int n0 = blockIdx.x * 32, k0 = blockIdx.y * 32;
    int tx = threadIdx.x, ty = threadIdx.y;
#pragma unroll
    for (int j = 0; j < 32; j += 8)
        s[ty + j][tx] = W[(size_t)(k0 + ty + j) * N + n0 + tx];
    __syncthreads();
#pragma unroll
    for (int j = 0; j < 32; j += 8) {
        float v = s[tx][ty + j];
        __nv_bfloat16 h = __float2bfloat16(v);
        size_t o = (size_t)(n0 + ty + j) * K + k0 + tx;
        Thi[o] = h;
        Tlo[o] = __float2bfloat16(v - __bfloat162float(h));
    }
}

// ================= bf16 GEMM (Wo projection, proven) =================
#define STG_A   0
#define STG_AL  10240
#define STG_B   20480
#define STG_BL  30720
#define STG_BYTES 40960
#define G_SMEM (2 * STG_BYTES)

__device__ __forceinline__ void gemm_cp_chunk(
    uint32_t st,
    const __nv_bfloat16* __restrict__ Ah, const __nv_bfloat16* __restrict__ Al,
    const __nv_bfloat16* __restrict__ Bh, const __nv_bfloat16* __restrict__ Bl,
    int bm, int bn, int K, int kc, int tid)
{
#pragma unroll
    for (int t = 0; t < 2; t++) {
        const int i = tid + t * 256;
        const int r = i >> 2, c = (i & 3) * 8;
        const uint32_t o = (uint32_t)(r * 80 + (i & 3) * 16);
        cp16(st + STG_A  + o, Ah + (size_t)(bm + r) * K + kc + c);
        cp16(st + STG_AL + o, Al + (size_t)(bm + r) * K + kc + c);
        cp16(st + STG_B  + o, Bh + (size_t)(bn + r) * K + kc + c);
        cp16(st + STG_BL + o, Bl + (size_t)(bn + r) * K + kc + c);
    }
}

__global__ __launch_bounds__(256, 2) void gemm_tc(
    const __nv_bfloat16* __restrict__ Ah, const __nv_bfloat16* __restrict__ Al,
    const __nv_bfloat16* __restrict__ Bh, const __nv_bfloat16* __restrict__ Bl,
    const float* __restrict__ bias, float* __restrict__ C, int N, int K)
{
    extern __shared__ char smem[];
    const int tid = threadIdx.x;
    const int lane = tid & 31;
    const int wid = tid >> 5;
    const int wm = wid & 1;
    const int wn = wid >> 1;
    const int bm = blockIdx.y * 128;
    const int bn = blockIdx.x * 128;

    float acc[4][4][4];
#pragma unroll
    for (int i = 0; i < 4; i++)
#pragma unroll
        for (int j = 0; j < 4; j++)
#pragma unroll
            for (int k = 0; k < 4; k++) acc[i][j][k] = 0.0f;

    const uint32_t sb0 = smem_u32(smem);
    const uint32_t aOff = (uint32_t)((wm * 64 + (lane & 15)) * 80 + ((lane >> 4) << 4));
    const uint32_t bOff = (uint32_t)((wn * 32 + (lane & 7) + ((lane >> 4) << 3)) * 80
                                     + (((lane >> 3) & 1) << 4));

    const int nch = K / 32;
    gemm_cp_chunk(sb0, Ah, Al, Bh, Bl, bm, bn, K, 0, tid);
    CP_COMMIT();
    for (int c = 0; c < nch; c++) {
        CP_WAIT0();
        __syncthreads();
        if (c + 1 < nch) {
            gemm_cp_chunk(sb0 + (uint32_t)(((c + 1) & 1) * STG_BYTES),
                          Ah, Al, Bh, Bl, bm, bn, K, (c + 1) * 32, tid);
            CP_COMMIT();
        }
        const uint32_t sb = sb0 + (uint32_t)((c & 1) * STG_BYTES);
#pragma unroll
        for (int ks = 0; ks < 2; ks++) {
            const uint32_t ko = (uint32_t)(ks * 32);
            uint32_t a0[4][4], a1[4][4], b0[2][4], b1[2][4];
#pragma unroll
            for (int mi = 0; mi < 4; mi++) ldsm4(a0[mi], sb + STG_A + aOff + mi * 1280 + ko);
#pragma unroll
            for (int nj = 0; nj < 2; nj++) ldsm4(b0[nj], sb + STG_B + bOff + nj * 1280 + ko);
#pragma unroll
            for (int nj = 0; nj < 2; nj++) ldsm4(b1[nj], sb + STG_BL + bOff + nj * 1280 + ko);
#pragma unroll
            for (int mi = 0; mi < 4; mi++) ldsm4(a1[mi], sb + STG_AL + aOff + mi * 1280 + ko);
#pragma unroll
            for (int mi = 0; mi < 4; mi++)
#pragma unroll
                for (int ni = 0; ni < 4; ni++)
                    mma16816(acc[mi][ni], a0[mi], &b0[ni >> 1][(ni & 1) * 2]);
#pragma unroll
            for (int mi = 0; mi < 4; mi++)
#pragma unroll
                for (int ni = 0; ni < 4; ni++)
                    mma16816(acc[mi][ni], a0[mi], &b1[ni >> 1][(ni & 1) * 2]);
#pragma unroll
            for (int mi = 0; mi < 4; mi++)
#pragma unroll
                for (int ni = 0; ni < 4; ni++)
                    mma16816(acc[mi][ni], a1[mi], &b0[ni >> 1][(ni & 1) * 2]);
        }
    }

    const int rbase = bm + wm * 64 + (lane >> 2);
    const int cbase = bn + wn * 32 + (lane & 3) * 2;
#pragma unroll
    for (int mi = 0; mi < 4; mi++) {
#pragma unroll
        for (int ni = 0; ni < 4; ni++) {
            const int col = cbase + ni * 8;
            const float2 bv = *(const float2*)(bias + col);
            const int r0 = rbase + mi * 16;
            float2 o0, o1;
            o0.x = acc[mi][ni][0] + bv.x; o0.y = acc[mi][ni][1] + bv.y;
            o1.x = acc[mi][ni][2] + bv.x; o1.y = acc[mi][ni][3] + bv.y;
            *(float2*)(C + (size_t)r0 * N + col) = o0;
            *(float2*)(C + (size_t)(r0 + 8) * N + col) = o1;
        }
    }
}

// ================= INT8 QKV GEMM + fused RoPE epilogue =================
// 16-bit fixed point: x = sx*(a*256+b). C = sx*sw*(65536*sum(aa') + 256*sum(ab'+ba'))
// smem rows: 32 B data + 16 pad = 48 B. 3-stage cp.async pipeline.
#define I8_AH 0
#define I8_AL 6144
#define I8_BH 12288
#define I8_BL 18432
#define I8_STG 24576
#define G8_SMEM (3 * I8_STG)

__global__ __launch_bounds__(256) void gemm_qkv_i8(const float* __restrict__ bias)
{
    extern __shared__ char smem[];
    const int tid = threadIdx.x;
    const int lane = tid & 31;
    const int wid = tid >> 5;
    const int wm = wid & 1;
    const int wn = wid >> 1;
    const int bm = blockIdx.y * 128;
    const int bn = blockIdx.x * 128;

    int accH[4][4][4], accM[4][4][4];
#pragma unroll
    for (int i = 0; i < 4; i++)
#pragma unroll
        for (int j = 0; j < 4; j++)
#pragma unroll
            for (int k = 0; k < 4; k++) { accH[i][j][k] = 0; accM[i][j][k] = 0; }

    const uint32_t sb0 = smem_u32(smem);
    const uint32_t aOff = (uint32_t)((wm * 64 + (lane & 15)) * 48 + ((lane >> 4) << 4));
    const uint32_t bOff = (uint32_t)((wn * 32 + (lane & 7) + ((lane >> 4) << 3)) * 48
                                     + (((lane >> 3) & 1) << 4));
    const int r = tid >> 1, hf = tid & 1;
    const uint32_t lo = (uint32_t)(r * 48 + hf * 16);

    auto load = [&](int kc, int st) {
        const uint32_t base = sb0 + (uint32_t)(st * I8_STG);
        cp16(base + I8_AH + lo, g_xq_h + (size_t)(bm + r) * 2048 + kc + hf * 16);
        cp16(base + I8_AL + lo, g_xq_l + (size_t)(bm + r) * 2048 + kc + hf * 16);
        cp16(base + I8_BH + lo, g_wq_h + (size_t)(bn + r) * 2048 + kc + hf * 16);
        cp16(base + I8_BL + lo, g_wq_l + (size_t)(bn + r) * 2048 + kc + hf * 16);
    };

    load(0, 0);  CP_COMMIT();
    load(32, 1); CP_COMMIT();

    for (int c = 0; c < 64; c++) {
        CP_WAIT1();
        __syncthreads();
        if (c + 2 < 64) load((c + 2) * 32, (c + 2) % 3);
        CP_COMMIT();   // unconditional: keeps 2 groups outstanding so WAIT1 retires chunk c

        const uint32_t sb = sb0 + (uint32_t)((c % 3) * I8_STG);
        uint32_t a0[4][4], a1[4][4], b0[2][4], b1[2][4];
#pragma unroll
        for (int mi = 0; mi < 4; mi++) ldsm4(a0[mi], sb + I8_AH + aOff + mi * 768);
#pragma unroll
        for (int nj = 0; nj < 2; nj++) ldsm4(b0[nj], sb + I8_BH + bOff + nj * 768);
#pragma unroll
        for (int nj = 0; nj < 2; nj++) ldsm4(b1[nj], sb + I8_BL + bOff + nj * 768);
#pragma unroll
        for (int mi = 0; mi < 4; mi++) ldsm4(a1[mi], sb + I8_AL + aOff + mi * 768);
#pragma unroll
        for (int mi = 0; mi < 4; mi++)
#pragma unroll
            for (int ni = 0; ni < 4; ni++)
                imma16832(accH[mi][ni], a0[mi], &b0[ni >> 1][(ni & 1) * 2]);
#pragma unroll
        for (int mi = 0; mi < 4; mi++)
#pragma unroll
            for (int ni = 0; ni < 4; ni++)
                imma16832(accM[mi][ni], a0[mi], &b1[ni >> 1][(ni & 1) * 2]);
#pragma unroll
        for (int mi = 0; mi < 4; mi++)
#pragma unroll
            for (int ni = 0; ni < 4; ni++)
                imma16832(accM[mi][ni], a1[mi], &b0[ni >> 1][(ni & 1) * 2]);
    }

    // ---------- fused RoPE/split epilogue (identical structure to bf16 version) ----------
    __syncthreads();

    const float sxw = (__uint_as_float(g_maxx_bits) * (1.0f / 32256.0f)) *
                      (__uint_as_float(g_maxw_bits) * (1.0f / 32256.0f));

    const int seg   = bn >> 11;          // 0=Q 1=K 2=V
    const int head  = (bn & 2047) >> 7;
    const int bidx  = bm >> 11;
    const int s_base = bm & 2047;
    const int bhh   = bidx * 16 + head;

    __nv_bfloat16* sh_hi = (__nv_bfloat16*)smem;            // 128x128 bf16 (64 KB <= 72 KB)
    __nv_bfloat16* sh_lo = (__nv_bfloat16*)(smem + 32768);

    const int rl = wm * 64 + (lane >> 2);
    const int cb = wn * 32 + (lane & 3) * 2;
    const float qscale = 0.08838834764831845f;

#pragma unroll
    for (int mi = 0; mi < 4; mi++) {
#pragma unroll
        for (int ni = 0; ni < 4; ni++) {
            const int c = cb + ni * 8;
            const float b0v = bias[bn + c], b1v = bias[bn + c + 1];
            float v0 = sxw * (65536.0f * (float)accH[mi][ni][0] + 256.0f * (float)accM[mi][ni][0]) + b0v;
            float v1 = sxw * (65536.0f * (float)accH[mi][ni][1] + 256.0f * (float)accM[mi][ni][1]) + b1v;
            float w0 = sxw * (65536.0f * (float)accH[mi][ni][2] + 256.0f * (float)accM[mi][ni][2]) + b0v;
            float w1 = sxw * (65536.0f * (float)accH[mi][ni][3] + 256.0f * (float)accM[mi][ni][3]) + b1v;
            const int r0 = rl + mi * 16, r1 = r0 + 8;
            if (seg < 2) {
                const int j = c >> 1;
                const float2 t0 = g_rope[(s_base + r0) * 64 + j];
                const float2 t1 = g_rope[(s_base + r1) * 64 + j];
                float a0v = v0 * t0.x - v1 * t0.y, o0 = v0 * t0.y + v1 * t0.x;
                float a1v = w0 * t1.x - w1 * t1.y, o1 = w0 * t1.y + w1 * t1.x;
                if (seg == 0) { a0v *= qscale; o0 *= qscale; a1v *= qscale; o1 *= qscale; }
                stage_split(sh_hi, sh_lo, r0 * 128 + j,      a0v);
                stage_split(sh_hi, sh_lo, r0 * 128 + j + 64, o0);
                stage_split(sh_hi, sh_lo, r1 * 128 + j,      a1v);
                stage_split(sh_hi, sh_lo, r1 * 128 + j + 64, o1);
            } else {
                stage_split(sh_hi, sh_lo, c * 128 + r0,       v0);
                stage_split(sh_hi, sh_lo, (c + 1) * 128 + r0, v1);
                stage_split(sh_hi, sh_lo, c * 128 + r1,       w0);
                stage_split(sh_hi, sh_lo, (c + 1) * 128 + r1, w1);
            }
        }
    }
    __syncthreads();

    if (seg < 2) {
        __nv_bfloat16* Hd = (seg == 0) ? g_qh : g_kh;
        __nv_bfloat16* Ld = (seg == 0) ? g_ql : g_kl;
        for (int i = tid; i < 2048; i += 256) {
            const int row = i >> 4, q = i & 15;
            const size_t eo = ((size_t)bhh * 2048 + s_base + row) * 128 + q * 8;
            *(uint4*)(Hd + eo) = *(const uint4*)(sh_hi + row * 128 + q * 8);
            *(uint4*)(Ld + eo) = *(const uint4*)(sh_lo + row * 128 + q * 8);
        }
    } else {
        for (int i = tid; i < 2048; i += 256) {
            const int d = i >> 4, q = i & 15;
            const size_t eo = ((size_t)(bhh * 128 + d)) * 2048 + s_base + q * 8;
            *(uint4*)(g_vth + eo) = *(const uint4*)(sh_hi + d * 128 + q * 8);
            *(uint4*)(g_vtl + eo) = *(const uint4*)(sh_lo + d * 128 + q * 8);
        }
    }
}

// ================= flash attention (unchanged from R9, passing) =================
#define AT_ROW   272
#define AT_VROW  144
#define AT_SMEM  143360

__global__ __launch_bounds__(256) void attn_tc()
{
    extern __shared__ char sm[];
    const uint32_t sb = smem_u32(sm);
    const int tid = threadIdx.x;
    const int lane = tid & 31;
    const int w = tid >> 5;
    const int qb = blockIdx.x;
    const int bh = blockIdx.y;

    const size_t hbase = (size_t)bh * 2048 * 128;
    const uint4* Qh = (const uint4*)(g_qh + hbase + (size_t)qb * 128 * 128);
    const uint4* Ql = (const uint4*)(g_ql + hbase + (size_t)qb * 128 * 128);
    const __nv_bfloat16* Khp = g_kh + hbase;
    const __nv_bfloat16* Klp = g_kl + hbase;
    const __nv_bfloat16* Vth = g_vth + (size_t)bh * 128 * 2048;
    const __nv_bfloat16* Vtl = g_vtl + (size_t)bh * 128 * 2048;

    for (int i = tid; i < 2048; i += 256) {
        const uint32_t off = (uint32_t)((i >> 4) * AT_ROW + (i & 15) * 16);
        *(uint4*)(sm + off) = Qh[i];
        *(uint4*)(sm + 34816 + off) = Ql[i];
    }
    __syncthreads();

    const uint32_t aOff = (uint32_t)((w * 16 + (lane & 15)) * AT_ROW + ((lane >> 4) << 4));
    uint32_t qfh[8][4], qfl[8][4];
#pragma unroll
    for (int kk = 0; kk < 8; kk++) {
        ldsm4(qfh[kk], sb + aOff + kk * 32);
        ldsm4(qfl[kk], sb + 34816 + aOff + kk * 32);
    }
    __syncthreads();

    const uint32_t bOff = (uint32_t)(((lane & 7) + ((lane >> 4) << 3)) * AT_ROW
                                     + (((lane >> 3) & 1) << 4));
    const uint32_t bV   = (uint32_t)(((lane & 7) + ((lane >> 4) << 3)) * AT_VROW
                                     + (((lane >> 3) & 1) << 4));

    float O[16][4];
#pragma unroll
    for (int i = 0; i < 16; i++)
#pragma unroll
        for (int j = 0; j < 4; j++) O[i][j] = 0.0f;
    float m0 = -30000.0f, m1 = -30000.0f, l0 = 0.0f, l1 = 0.0f;
    const int g = lane >> 2, lam = lane & 3;

    auto load_chunk = [&](int kc, int st) {
        const uint32_t kbase = sb + (uint32_t)(st * 34816);
        const uint32_t vbase = sb + 69632u + (uint32_t)(st * 36864);
#pragma unroll
        for (int t = 0; t < 4; t++) {
            const int i = tid + t * 256;
            const int kr = i >> 4, kq = i & 15;
            cp16(kbase + kr * AT_ROW + kq * 16,         Khp + (size_t)(kc + kr) * 128 + kq * 8);
            cp16(kbase + 17408 + kr * AT_ROW + kq * 16, Klp + (size_t)(kc + kr) * 128 + kq * 8);
            const int vr = i >> 3, vq = i & 7;
            cp16(vbase + vr * AT_VROW + vq * 16,         Vth + (size_t)vr * 2048 + kc + vq * 8);
            cp16(vbase + 18432 + vr * AT_VROW + vq * 16, Vtl + (size_t)vr * 2048 + kc + vq * 8);
        }
    };

    load_chunk(0, 0);
    CP_COMMIT();

    for (int cidx = 0; cidx < 32; cidx++) {
        CP_WAIT0();
        __syncthreads();
        if (cidx + 1 < 32) {
            load_chunk((cidx + 1) * 64, (cidx + 1) & 1);
            CP_COMMIT();
        }
        const uint32_t kst = sb + (uint32_t)((cidx & 1) * 34816);
        const uint32_t vst = sb + 69632u + (uint32_t)((cidx & 1) * 36864);

        float S[8][4];
#pragma unroll
        for (int t = 0; t < 8; t++)
#pragma unroll
            for (int j = 0; j < 4; j++) S[t][j] = 0.0f;

#pragma unroll
        for (int kk = 0; kk < 8; kk++) {
#pragma unroll
            for (int kg = 0; kg < 4; kg++) {
                uint32_t kbh[4], kbl[4];
                ldsm4(kbh, kst + bOff + kg * (16 * AT_ROW) + kk * 32);
                ldsm4(kbl, kst + 17408 + bOff + kg * (16 * AT_ROW) + kk * 32);
                mma16816(S[2 * kg],     qfh[kk], kbh + 0);
                mma16816(S[2 * kg + 1], qfh[kk], kbh + 2);
                mma16816(S[2 * kg],     qfh[kk], kbl + 0);
                mma16816(S[2 * kg + 1], qfh[kk], kbl + 2);
                mma16816(S[2 * kg],     qfl[kk], kbh + 0);
                mma16816(S[2 * kg + 1], qfl[kk], kbh + 2);
            }
        }

        float mx0 = -30000.0f, mx1 = -30000.0f;
#pragma unroll
        for (int t = 0; t < 8; t++) {
            mx0 = fmaxf(mx0, fmaxf(S[t][0], S[t][1]));
            mx1 = fmaxf(mx1, fmaxf(S[t][2], S[t][3]));
        }
        mx0 = fmaxf(mx0, __shfl_xor_sync(0xffffffff, mx0, 1));
        mx0 = fmaxf(mx0, __shfl_xor_sync(0xffffffff, mx0, 2));
        mx1 = fmaxf(mx1, __shfl_xor_sync(0xffffffff, mx1, 1));
        mx1 = fmaxf(mx1, __shfl_xor_sync(0xffffffff, mx1, 2));

        const float nm0 = fmaxf(m0, mx0);
        const float nm1 = fmaxf(m1, mx1);
        const float al0 = __expf(fminf(m0 - nm0, 0.0f));
        const float al1 = __expf(fminf(m1 - nm1, 0.0f));
        m0 = nm0; m1 = nm1;

        float s0 = 0.0f, s1 = 0.0f;
#pragma unroll
        for (int t = 0; t < 8; t++) {
            S[t][0] = __expf(fminf(S[t][0] - m0, 0.0f));
            S[t][1] = __expf(fminf(S[t][1] - m0, 0.0f));
            S[t][2] = __expf(fminf(S[t][2] - m1, 0.0f));
            S[t][3] = __expf(fminf(S[t][3] - m1, 0.0f));
            s0 += S[t][0] + S[t][1];
            s1 += S[t][2] + S[t][3];
        }
        l0 = l0 * al0 + s0;
        l1 = l1 * al1 + s1;
#pragma unroll
        for (int nt = 0; nt < 16; nt++) {
            O[nt][0] *= al0; O[nt][1] *= al0;
            O[nt][2] *= al1; O[nt][3] *= al1;
        }

#pragma unroll
        for (int kt = 0; kt < 4; kt++) {
            uint32_t ph[4], pl[4];
            {
                __nv_bfloat162 h;
                h = __floats2bfloat162_rn(S[2 * kt][0], S[2 * kt][1]);
                ph[0] = bf2_bits(h);
                pl[0] = bf2_bits(__floats2bfloat162_rn(S[2 * kt][0] - __bfloat162float(h.x),
                                                       S[2 * kt][1] - __bfloat162float(h.y)));
                h = __floats2bfloat162_rn(S[2 * kt][2], S[2 * kt][3]);
                ph[1] = bf2_bits(h);
                pl[1] = bf2_bits(__floats2bfloat162_rn(S[2 * kt][2] - __bfloat162float(h.x),
                                                       S[2 * kt][3] - __bfloat162float(h.y)));
                h = __floats2bfloat162_rn(S[2 * kt + 1][0], S[2 * kt + 1][1]);
                ph[2] = bf2_bits(h);
                pl[2] = bf2_bits(__floats2bfloat162_rn(S[2 * kt + 1][0] - __bfloat162float(h.x),
                                                       S[2 * kt + 1][1] - __bfloat162float(h.y)));
                h = __floats2bfloat162_rn(S[2 * kt + 1][2], S[2 * kt + 1][3]);
                ph[3] = bf2_bits(h);
                pl[3] = bf2_bits(__floats2bfloat162_rn(S[2 * kt + 1][2] - __bfloat162float(h.x),
                                                       S[2 * kt + 1][3] - __bfloat162float(h.y)));
            }
#pragma unroll
            for (int j = 0; j < 8; j++) {
                uint32_t vbh[4], vbl[4];
                ldsm4(vbh, vst + bV + j * (16 * AT_VROW) + kt * 32);
                ldsm4(vbl, vst + 18432 + bV + j * (16 * AT_VROW) + kt * 32);
                mma16816(O[2 * j],     ph, vbh + 0);
                mma16816(O[2 * j + 1], ph, vbh + 2);
                mma16816(O[2 * j],     ph, vbl + 0);
                mma16816(O[2 * j + 1], ph, vbl + 2);
                mma16816(O[2 * j],     pl, vbh + 0);
                mma16816(O[2 * j + 1], pl, vbh + 2);
            }
        }
    }

    l0 += __shfl_xor_sync(0xffffffff, l0, 1);
    l0 += __shfl_xor_sync(0xffffffff, l0, 2);
    l1 += __shfl_xor_sync(0xffffffff, l1, 1);
    l1 += __shfl_xor_sync(0xffffffff, l1, 2);
    const float inv0 = 1.0f / l0;
    const float inv1 = 1.0f / l1;

    const int bb = bh >> 4, hh2 = bh & 15;
    const int row0 = qb * 128 + w * 16 + g;
    const size_t base0 = (size_t)(bb * 2048 + row0) * 2048 + hh2 * 128 + lam * 2;
    const size_t base1 = base0 + (size_t)8 * 2048;

#pragma unroll
    for (int nt = 0; nt < 16; nt++) {
        float x0 = O[nt][0] * inv0, x1 = O[nt][1] * inv0;
        __nv_bfloat162 hx = __floats2bfloat162_rn(x0, x1);
        __nv_bfloat162 lx = __floats2bfloat162_rn(x0 - __bfloat162float(hx.x),
                                                  x1 - __bfloat162float(hx.y));
        *(uint32_t*)(g_att_hi + base0 + nt * 8) = bf2_bits(hx);
        *(uint32_t*)(g_att_lo + base0 + nt * 8) = bf2_bits(lx);

        float x2 = O[nt][2] * inv1, x3 = O[nt][3] * inv1;
        hx = __floats2bfloat162_rn(x2, x3);
        lx = __floats2bfloat162_rn(x2 - __bfloat162float(hx.x),
                                   x3 - __bfloat162float(hx.y));
        *(uint32_t*)(g_att_hi + base1 + nt * 8) = bf2_bits(hx);
        *(uint32_t*)(g_att_lo + base1 + nt * 8) = bf2_bits(lx);
    }
}

// ================= launch =================
extern "C" void kernel_launch(void* const* d_in, const int* in_sizes, int n_in,
                              void* d_out, int out_size)
{
    const float* x    = (const float*)d_in[0];
    const float* Wqkv = (const float*)d_in[1];
    const float* bqkv = (const float*)d_in[2];
    const float* Wo   = (const float*)d_in[3];
    const float* bo   = (const float*)d_in[4];
    float* out = (float*)d_out;

    __nv_bfloat16 *ah, *al, *woh, *wol;
    unsigned *mx, *mw;
    cudaGetSymbolAddress((void**)&ah, g_att_hi);
    cudaGetSymbolAddress((void**)&al, g_att_lo);
    cudaGetSymbolAddress((void**)&woh, g_WoT_hi);
    cudaGetSymbolAddress((void**)&wol, g_WoT_lo);
    cudaGetSymbolAddress((void**)&mx, g_maxx_bits);
    cudaGetSymbolAddress((void**)&mw, g_maxw_bits);

    cudaFuncSetAttribute(gemm_tc, cudaFuncAttributeMaxDynamicSharedMemorySize, G_SMEM);
    cudaFuncSetAttribute(gemm_qkv_i8, cudaFuncAttributeMaxDynamicSharedMemorySize, G8_SMEM);
    cudaFuncSetAttribute(attn_tc, cudaFuncAttributeMaxDynamicSharedMemorySize, AT_SMEM);

    // prep: rope table, per-tensor maxes (idempotent), quantize, Wo transpose
    rope_table_kernel<<<(2048 * 64) / 256, 256>>>();
    maxabs_kernel<<<592, 256>>>(x, 4096 * 2048, mx);
    maxabs_kernel<<<592, 256>>>(Wqkv, 2048 * 6144, mw);
    quant_x_kernel<<<(4096 * 2048) / 256, 256>>>(x, 4096 * 2048);
    quantT_w_kernel<<<dim3(6144 / 32, 2048 / 32), dim3(32, 8)>>>(Wqkv, 2048, 6144);
    transpose_split<<<dim3(2048 / 32, 2048 / 32), dim3(32, 8)>>>(Wo, woh, wol, 2048, 2048);

    // 1) QKV projection (int8 IMMA) + fused RoPE/head-split/V-transpose
    gemm_qkv_i8<<<dim3(48, 32), 256, G8_SMEM>>>(bqkv);

    // 2) Tensor-core flash attention (bf16)
    attn_tc<<<dim3(16, 32), 256, AT_SMEM>>>();

    // 3) Output projection (bf16)
    gemm_tc<<<dim3(16, 32), 256, G_SMEM>>>(ah, al, woh, wol, bo, out, 2048, 2048);
}

// round 11
// speedup vs baseline: 1.9543x; 1.9543x over previous
#include <cuda_runtime.h>
#include <cuda_bf16.h>
#include <cstdint>
#include <math.h>

// ================= scratch =================
__device__ __nv_bfloat16 g_x_hi[4096 * 2048];
__device__ __nv_bfloat16 g_x_lo[4096 * 2048];
__device__ __nv_bfloat16 g_att_hi[4096 * 2048];
__device__ __nv_bfloat16 g_att_lo[4096 * 2048];
__device__ __nv_bfloat16 g_WqkvT_hi[6144 * 2048];
__device__ __nv_bfloat16 g_WqkvT_lo[6144 * 2048];
__device__ __nv_bfloat16 g_WoT_hi[2048 * 2048];
__device__ __nv_bfloat16 g_WoT_lo[2048 * 2048];
__device__ __nv_bfloat16 g_qh[4096 * 2048];
__device__ __nv_bfloat16 g_ql[4096 * 2048];
__device__ __nv_bfloat16 g_kh[4096 * 2048];
__device__ __nv_bfloat16 g_kl[4096 * 2048];
__device__ __nv_bfloat16 g_vth[4096 * 2048];
__device__ __nv_bfloat16 g_vtl[4096 * 2048];
__device__ float2 g_rope[2048 * 64];

// ================= helpers =================
__device__ __forceinline__ uint32_t smem_u32(const void* p) {
    uint32_t a;
    asm("{ .reg .u64 t; cvta.to.shared.u64 t, %1; cvt.u32.u64 %0, t; }" : "=r"(a) : "l"(p));
    return a;
}
__device__ __forceinline__ void ldsm4(uint32_t (&r)[4], uint32_t addr) {
    asm volatile("ldmatrix.sync.aligned.m8n8.x4.shared.b16 {%0,%1,%2,%3}, [%4];"
        : "=r"(r[0]), "=r"(r[1]), "=r"(r[2]), "=r"(r[3]) : "r"(addr));
}
__device__ __forceinline__ void mma16816(float* c, const uint32_t* a, const uint32_t* b) {
    asm volatile("mma.sync.aligned.m16n8k16.row.col.f32.bf16.bf16.f32 "
        "{%0,%1,%2,%3}, {%4,%5,%6,%7}, {%8,%9}, {%0,%1,%2,%3};"
        : "+f"(c[0]), "+f"(c[1]), "+f"(c[2]), "+f"(c[3])
        : "r"(a[0]), "r"(a[1]), "r"(a[2]), "r"(a[3]), "r"(b[0]), "r"(b[1]));
}
__device__ __forceinline__ void cp16(uint32_t sa, const void* g) {
    asm volatile("cp.async.cg.shared.global [%0], [%1], 16;" :: "r"(sa), "l"(g));
}
#define CP_COMMIT() asm volatile("cp.async.commit_group;" ::: "memory")
#define CP_WAIT0()  asm volatile("cp.async.wait_group 0;" ::: "memory")
__device__ __forceinline__ uint32_t bf2_bits(__nv_bfloat162 v) {
    return *reinterpret_cast<uint32_t*>(&v);
}
__device__ __forceinline__ void stage_split(__nv_bfloat16* hi, __nv_bfloat16* lo,
                                            int off, float v) {
    __nv_bfloat16 h = __float2bfloat16(v);
    hi[off] = h;
    lo[off] = __float2bfloat16(v - __bfloat162float(h));
}

// ================= prep kernels =================
__global__ void split_convert(const float* __restrict__ in,
                              __nv_bfloat16* __restrict__ hi, __nv_bfloat16* __restrict__ lo, int n) {
    int i = blockIdx.x * blockDim.x + threadIdx.x;
    if (i >= n) return;
    float v = in[i];
    __nv_bfloat16 h = __float2bfloat16(v);
    hi[i] = h;
    lo[i] = __float2bfloat16(v - __bfloat162float(h));
}

__global__ void rope_table_kernel()
{
    const int idx = blockIdx.x * blockDim.x + threadIdx.x;
    const int j = idx & 63;
    const int s = idx >> 6;
    const float theta = 1.0f / powf(10000.0f, (float)(2 * j) / 128.0f);
    float sn, cs;
    sincosf((float)s * theta, &sn, &cs);
    g_rope[idx] = make_float2(cs, sn);
}

__global__ void transpose_split(const float* __restrict__ W,
                                __nv_bfloat16* __restrict__ Thi, __nv_bfloat16* __restrict__ Tlo,
                                int K, int N) {
    __shared__ float s[32][33];
    int n0 = blockIdx.x * 32, k0 = blockIdx.y * 32;
    int tx = threadIdx.x, ty = threadIdx.y;
#pragma unroll
    for (int j = 0; j < 32; j += 8)
        s[ty + j][tx] = W[(size_t)(k0 + ty + j) * N + n0 + tx];
    __syncthreads();
#pragma unroll
    for (int j = 0; j < 32; j += 8) {
        float v = s[tx][ty + j];
        __nv_bfloat16 h = __float2bfloat16(v);
        size_t o = (size_t)(n0 + ty + j) * K + k0 + tx;
        Thi[o] = h;
        Tlo[o] = __float2bfloat16(v - __bfloat162float(h));
    }
}

// ================= GEMM mainloop (cp.async double-buffered, proven R8/R9) =================
#define STG_A   0
#define STG_AL  10240
#define STG_B   20480
#define STG_BL  30720
#define STG_BYTES 40960
#define G_SMEM (2 * STG_BYTES)

__device__ __forceinline__ void gemm_cp_chunk(
    uint32_t st,
    const __nv_bfloat16* __restrict__ Ah, const __nv_bfloat16* __restrict__ Al,
    const __nv_bfloat16* __restrict__ Bh, const __nv_bfloat16* __restrict__ Bl,
    int bm, int bn, int K, int kc, int tid)
{
#pragma unroll
    for (int t = 0; t < 2; t++) {
        const int i = tid + t * 256;
        const int r = i >> 2, c = (i & 3) * 8;
        const uint32_t o = (uint32_t)(r * 80 + (i & 3) * 16);
        cp16(st + STG_A  + o, Ah + (size_t)(bm + r) * K + kc + c);
        cp16(st + STG_AL + o, Al + (size_t)(bm + r) * K + kc + c);
        cp16(st + STG_B  + o, Bh + (size_t)(bn + r) * K + kc + c);
        cp16(st + STG_BL + o, Bl + (size_t)(bn + r) * K + kc + c);
    }
}

#define GEMM_MAINLOOP(Ah, Al, Bh, Bl, K)                                            \
    float acc[4][4][4];                                                             \
    _Pragma("unroll") for (int i = 0; i < 4; i++)                                   \
    _Pragma("unroll") for (int j = 0; j < 4; j++)                                   \
    _Pragma("unroll") for (int k = 0; k < 4; k++) acc[i][j][k] = 0.0f;              \
    const uint32_t sb0 = smem_u32(smem);                                            \
    const uint32_t aOff = (uint32_t)((wm * 64 + (lane & 15)) * 80 + ((lane >> 4) << 4)); \
    const uint32_t bOff = (uint32_t)((wn * 32 + (lane & 7) + ((lane >> 4) << 3)) * 80    \
                                     + (((lane >> 3) & 1) << 4));                   \
    const int nch = (K) / 32;                                                       \
    gemm_cp_chunk(sb0, Ah, Al, Bh, Bl, bm, bn, K, 0, tid);                          \
    CP_COMMIT();                                                                    \
    for (int c = 0; c < nch; c++) {                                                 \
        CP_WAIT0();                                                                 \
        __syncthreads();                                                            \
        if (c + 1 < nch) {                                                          \
            gemm_cp_chunk(sb0 + (uint32_t)(((c + 1) & 1) * STG_BYTES),              \
                          Ah, Al, Bh, Bl, bm, bn, K, (c + 1) * 32, tid);            \
            CP_COMMIT();                                                            \
        }                                                                           \
        const uint32_t sb = sb0 + (uint32_t)((c & 1) * STG_BYTES);                  \
        _Pragma("unroll")                                                           \
        for (int ks = 0; ks < 2; ks++) {                                            \
            const uint32_t ko = (uint32_t)(ks * 32);                                \
            uint32_t a0[4][4], a1[4][4], b0[2][4], b1[2][4];                        \
            _Pragma("unroll") for (int mi = 0; mi < 4; mi++)                        \
                ldsm4(a0[mi], sb + STG_A + aOff + mi * 1280 + ko);                  \
            _Pragma("unroll") for (int nj = 0; nj < 2; nj++)                        \
                ldsm4(b0[nj], sb + STG_B + bOff + nj * 1280 + ko);                  \
            _Pragma("unroll") for (int nj = 0; nj < 2; nj++)                        \
                ldsm4(b1[nj], sb + STG_BL + bOff + nj * 1280 + ko);                 \
            _Pragma("unroll") for (int mi = 0; mi < 4; mi++)                        \
                ldsm4(a1[mi], sb + STG_AL + aOff + mi * 1280 + ko);                 \
            _Pragma("unroll") for (int mi = 0; mi < 4; mi++)                        \
            _Pragma("unroll") for (int ni = 0; ni < 4; ni++)                        \
                mma16816(acc[mi][ni], a0[mi], &b0[ni >> 1][(ni & 1) * 2]);          \
            _Pragma("unroll") for (int mi = 0; mi < 4; mi++)                        \
            _Pragma("unroll") for (int ni = 0; ni < 4; ni++)                        \
                mma16816(acc[mi][ni], a0[mi], &b1[ni >> 1][(ni & 1) * 2]);          \
            _Pragma("unroll") for (int mi = 0; mi < 4; mi++)                        \
            _Pragma("unroll") for (int ni = 0; ni < 4; ni++)                        \
                mma16816(acc[mi][ni], a1[mi], &b0[ni >> 1][(ni & 1) * 2]);          \
        }                                                                           \
    }

// ================= GEMM #2: out-proj (float out + bias) =================
__global__ __launch_bounds__(256, 2) void gemm_tc(
    const __nv_bfloat16* __restrict__ Ah, const __nv_bfloat16* __restrict__ Al,
    const __nv_bfloat16* __restrict__ Bh, const __nv_bfloat16* __restrict__ Bl,
    const float* __restrict__ bias, float* __restrict__ C, int N, int K)
{
    extern __shared__ char smem[];
    const int tid = threadIdx.x;
    const int lane = tid & 31;
    const int wid = tid >> 5;
    const int wm = wid & 1;
    const int wn = wid >> 1;
    const int bm = blockIdx.y * 128;
    const int bn = blockIdx.x * 128;

    GEMM_MAINLOOP(Ah, Al, Bh, Bl, K)

    const int rbase = bm + wm * 64 + (lane >> 2);
    const int cbase = bn + wn * 32 + (lane & 3) * 2;
#pragma unroll
    for (int mi = 0; mi < 4; mi++) {
#pragma unroll
        for (int ni = 0; ni < 4; ni++) {
            const int col = cbase + ni * 8;
            const float2 bv = *(const float2*)(bias + col);
            const int r0 = rbase + mi * 16;
            float2 o0, o1;
            o0.x = acc[mi][ni][0] + bv.x; o0.y = acc[mi][ni][1] + bv.y;
            o1.x = acc[mi][ni][2] + bv.x; o1.y = acc[mi][ni][3] + bv.y;
            *(float2*)(C + (size_t)r0 * N + col) = o0;
            *(float2*)(C + (size_t)(r0 + 8) * N + col) = o1;
        }
    }
}

// ================= GEMM #1: QKV projection + fused RoPE (table) =================
__global__ __launch_bounds__(256, 2) void gemm_qkv_rope(
    const __nv_bfloat16* __restrict__ Ah, const __nv_bfloat16* __restrict__ Al,
    const __nv_bfloat16* __restrict__ Bh, const __nv_bfloat16* __restrict__ Bl,
    const float* __restrict__ bias)
{
    extern __shared__ char smem[];
    const int tid = threadIdx.x;
    const int lane = tid & 31;
    const int wid = tid >> 5;
    const int wm = wid & 1;
    const int wn = wid >> 1;
    const int bm = blockIdx.y * 128;
    const int bn = blockIdx.x * 128;
    const int K = 2048;

    GEMM_MAINLOOP(Ah, Al, Bh, Bl, K)

    __syncthreads();

    const int seg   = bn >> 11;          // 0=Q 1=K 2=V
    const int head  = (bn & 2047) >> 7;
    const int bidx  = bm >> 11;
    const int s_base = bm & 2047;
    const int bhh   = bidx * 16 + head;

    __nv_bfloat16* sh_hi = (__nv_bfloat16*)smem;
    __nv_bfloat16* sh_lo = (__nv_bfloat16*)(smem + 32768);

    const int rl = wm * 64 + (lane >> 2);
    const int cb = wn * 32 + (lane & 3) * 2;
    const float qscale = 0.08838834764831845f;

#pragma unroll
    for (int mi = 0; mi < 4; mi++) {
#pragma unroll
        for (int ni = 0; ni < 4; ni++) {
            const int c = cb + ni * 8;
            const float b0 = bias[bn + c], b1 = bias[bn + c + 1];
            float v0 = acc[mi][ni][0] + b0, v1 = acc[mi][ni][1] + b1;
            float w0 = acc[mi][ni][2] + b0, w1 = acc[mi][ni][3] + b1;
            const int r0 = rl + mi * 16, r1 = r0 + 8;
            if (seg < 2) {
                const int j = c >> 1;
                const float2 t0 = g_rope[(s_base + r0) * 64 + j];
                const float2 t1 = g_rope[(s_base + r1) * 64 + j];
                float a0 = v0 * t0.x - v1 * t0.y, o0 = v0 * t0.y + v1 * t0.x;
                float a1 = w0 * t1.x - w1 * t1.y, o1 = w0 * t1.y + w1 * t1.x;
                if (seg == 0) { a0 *= qscale; o0 *= qscale; a1 *= qscale; o1 *= qscale; }
                stage_split(sh_hi, sh_lo, r0 * 128 + j,      a0);
                stage_split(sh_hi, sh_lo, r0 * 128 + j + 64, o0);
                stage_split(sh_hi, sh_lo, r1 * 128 + j,      a1);
                stage_split(sh_hi, sh_lo, r1 * 128 + j + 64, o1);
            } else {
                stage_split(sh_hi, sh_lo, c * 128 + r0,       v0);
                stage_split(sh_hi, sh_lo, (c + 1) * 128 + r0, v1);
                stage_split(sh_hi, sh_lo, c * 128 + r1,       w0);
                stage_split(sh_hi, sh_lo, (c + 1) * 128 + r1, w1);
            }
        }
    }
    __syncthreads();

    if (seg < 2) {
        __nv_bfloat16* Hd = (seg == 0) ? g_qh : g_kh;
        __nv_bfloat16* Ld = (seg == 0) ? g_ql : g_kl;
        for (int i = tid; i < 2048; i += 256) {
            const int row = i >> 4, q = i & 15;
            const size_t eo = ((size_t)bhh * 2048 + s_base + row) * 128 + q * 8;
            *(uint4*)(Hd + eo) = *(const uint4*)(sh_hi + row * 128 + q * 8);
            *(uint4*)(Ld + eo) = *(const uint4*)(sh_lo + row * 128 + q * 8);
        }
    } else {
        for (int i = tid; i < 2048; i += 256) {
            const int d = i >> 4, q = i & 15;
            const size_t eo = ((size_t)(bhh * 128 + d)) * 2048 + s_base + q * 8;
            *(uint4*)(g_vth + eo) = *(const uint4*)(sh_hi + d * 128 + q * 8);
            *(uint4*)(g_vtl + eo) = *(const uint4*)(sh_lo + d * 128 + q * 8);
        }
    }
}

// ================= flash attention: 64 queries/CTA, 32-key chunks, 2 CTAs/SM =================
// K rows 272B (128 bf16 + pad). V^T rows 80B (32 keys + pad).
// K stage s: s*17408 (hi), +8704 (lo). V stage s: 34816 + s*20480 (hi), +10240 (lo).
#define AT_ROW   272
#define AT_VROW  80
#define AT_SMEM  75776

__global__ __launch_bounds__(128) void attn_tc()
{
    extern __shared__ char sm[];
    const uint32_t sb = smem_u32(sm);
    const int tid = threadIdx.x;
    const int lane = tid & 31;
    const int w = tid >> 5;          // 0..3
    const int qb = blockIdx.x;       // 0..31 (64-query tiles)
    const int bh = blockIdx.y;

    const size_t hbase = (size_t)bh * 2048 * 128;
    const uint4* Qh = (const uint4*)(g_qh + hbase + (size_t)qb * 64 * 128);
    const uint4* Ql = (const uint4*)(g_ql + hbase + (size_t)qb * 64 * 128);
    const __nv_bfloat16* Khp = g_kh + hbase;
    const __nv_bfloat16* Klp = g_kl + hbase;
    const __nv_bfloat16* Vth = g_vth + (size_t)bh * 128 * 2048;
    const __nv_bfloat16* Vtl = g_vtl + (size_t)bh * 128 * 2048;

    // stage Q (64 rows x 16 uint4) into K buffers temporarily: Qh @0, Ql @17408
    for (int i = tid; i < 1024; i += 128) {
        const uint32_t off = (uint32_t)((i >> 4) * AT_ROW + (i & 15) * 16);
        *(uint4*)(sm + off) = Qh[i];
        *(uint4*)(sm + 17408 + off) = Ql[i];
    }
    __syncthreads();

    const uint32_t aOff = (uint32_t)((w * 16 + (lane & 15)) * AT_ROW + ((lane >> 4) << 4));
    uint32_t qfh[8][4], qfl[8][4];
#pragma unroll
    for (int kk = 0; kk < 8; kk++) {
        ldsm4(qfh[kk], sb + aOff + kk * 32);
        ldsm4(qfl[kk], sb + 17408 + aOff + kk * 32);
    }
    __syncthreads();

    const uint32_t bOff = (uint32_t)(((lane & 7) + ((lane >> 4) << 3)) * AT_ROW
                                     + (((lane >> 3) & 1) << 4));
    const uint32_t bV   = (uint32_t)(((lane & 7) + ((lane >> 4) << 3)) * AT_VROW
                                     + (((lane >> 3) & 1) << 4));

    float O[16][4];
#pragma unroll
    for (int i = 0; i < 16; i++)
#pragma unroll
        for (int j = 0; j < 4; j++) O[i][j] = 0.0f;
    float m0 = -30000.0f, m1 = -30000.0f, l0 = 0.0f, l1 = 0.0f;
    const int g = lane >> 2, lam = lane & 3;

    auto load_chunk = [&](int kc, int st) {
        const uint32_t kbase = sb + (uint32_t)(st * 17408);
        const uint32_t vbase = sb + 34816u + (uint32_t)(st * 20480);
#pragma unroll
        for (int t = 0; t < 4; t++) {
            const int i = tid + t * 128;            // 0..511
            const int kr = i >> 4, kq = i & 15;     // K: 32 rows x 16 uint4
            cp16(kbase + kr * AT_ROW + kq * 16,        Khp + (size_t)(kc + kr) * 128 + kq * 8);
            cp16(kbase + 8704 + kr * AT_ROW + kq * 16, Klp + (size_t)(kc + kr) * 128 + kq * 8);
            const int vr = i >> 2, vq = i & 3;      // V: 128 rows x 4 uint4
            cp16(vbase + vr * AT_VROW + vq * 16,         Vth + (size_t)vr * 2048 + kc + vq * 8);
            cp16(vbase + 10240 + vr * AT_VROW + vq * 16, Vtl + (size_t)vr * 2048 + kc + vq * 8);
        }
    };

    load_chunk(0, 0);
    CP_COMMIT();

    for (int cidx = 0; cidx < 64; cidx++) {
        CP_WAIT0();
        __syncthreads();
        if (cidx + 1 < 64) {
            load_chunk((cidx + 1) * 32, (cidx + 1) & 1);
            CP_COMMIT();
        }
        const uint32_t kst = sb + (uint32_t)((cidx & 1) * 17408);
        const uint32_t vst = sb + 34816u + (uint32_t)((cidx & 1) * 20480);

        // ---- S = Q @ K^T (3-term split), 32 keys -> S[4][4] ----
        float S[4][4];
#pragma unroll
        for (int t = 0; t < 4; t++)
#pragma unroll
            for (int j = 0; j < 4; j++) S[t][j] = 0.0f;

#pragma unroll
        for (int kk = 0; kk < 8; kk++) {
#pragma unroll
            for (int kg = 0; kg < 2; kg++) {
                uint32_t kbh[4], kbl[4];
                ldsm4(kbh, kst + bOff + kg * (16 * AT_ROW) + kk * 32);
                ldsm4(kbl, kst + 8704 + bOff + kg * (16 * AT_ROW) + kk * 32);
                mma16816(S[2 * kg],     qfh[kk], kbh + 0);
                mma16816(S[2 * kg + 1], qfh[kk], kbh + 2);
                mma16816(S[2 * kg],     qfh[kk], kbl + 0);
                mma16816(S[2 * kg + 1], qfh[kk], kbl + 2);
                mma16816(S[2 * kg],     qfl[kk], kbh + 0);
                mma16816(S[2 * kg + 1], qfl[kk], kbh + 2);
            }
        }

        // ---- online softmax ----
        float mx0 = -30000.0f, mx1 = -30000.0f;
#pragma unroll
        for (int t = 0; t < 4; t++) {
            mx0 = fmaxf(mx0, fmaxf(S[t][0], S[t][1]));
            mx1 = fmaxf(mx1, fmaxf(S[t][2], S[t][3]));
        }
        mx0 = fmaxf(mx0, __shfl_xor_sync(0xffffffff, mx0, 1));
        mx0 = fmaxf(mx0, __shfl_xor_sync(0xffffffff, mx0, 2));
        mx1 = fmaxf(mx1, __shfl_xor_sync(0xffffffff, mx1, 1));
        mx1 = fmaxf(mx1, __shfl_xor_sync(0xffffffff, mx1, 2));

        const float nm0 = fmaxf(m0, mx0);
        const float nm1 = fmaxf(m1, mx1);
        const float al0 = __expf(fminf(m0 - nm0, 0.0f));
        const float al1 = __expf(fminf(m1 - nm1, 0.0f));
        m0 = nm0; m1 = nm1;

        float s0 = 0.0f, s1 = 0.0f;
#pragma unroll
        for (int t = 0; t < 4; t++) {
            S[t][0] = __expf(fminf(S[t][0] - m0, 0.0f));
            S[t][1] = __expf(fminf(S[t][1] - m0, 0.0f));
            S[t][2] = __expf(fminf(S[t][2] - m1, 0.0f));
            S[t][3] = __expf(fminf(S[t][3] - m1, 0.0f));
            s0 += S[t][0] + S[t][1];
            s1 += S[t][2] + S[t][3];
        }
        l0 = l0 * al0 + s0;
        l1 = l1 * al1 + s1;
#pragma unroll
        for (int nt = 0; nt < 16; nt++) {
            O[nt][0] *= al0; O[nt][1] *= al0;
            O[nt][2] *= al1; O[nt][3] *= al1;
        }

        // ---- O += P @ V, P converted in registers (acc layout == A-frag layout) ----
#pragma unroll
        for (int kt = 0; kt < 2; kt++) {
            uint32_t ph[4], pl[4];
            {
                __nv_bfloat162 h;
                h = __floats2bfloat162_rn(S[2 * kt][0], S[2 * kt][1]);
                ph[0] = bf2_bits(h);
                pl[0] = bf2_bits(__floats2bfloat162_rn(S[2 * kt][0] - __bfloat162float(h.x),
                                                       S[2 * kt][1] - __bfloat162float(h.y)));
                h = __floats2bfloat162_rn(S[2 * kt][2], S[2 * kt][3]);
                ph[1] = bf2_bits(h);
                pl[1] = bf2_bits(__floats2bfloat162_rn(S[2 * kt][2] - __bfloat162float(h.x),
                                                       S[2 * kt][3] - __bfloat162float(h.y)));
                h = __floats2bfloat162_rn(S[2 * kt + 1][0], S[2 * kt + 1][1]);
                ph[2] = bf2_bits(h);
                pl[2] = bf2_bits(__floats2bfloat162_rn(S[2 * kt + 1][0] - __bfloat162float(h.x),
                                                       S[2 * kt + 1][1] - __bfloat162float(h.y)));
                h = __floats2bfloat162_rn(S[2 * kt + 1][2], S[2 * kt + 1][3]);
                ph[3] = bf2_bits(h);
                pl[3] = bf2_bits(__floats2bfloat162_rn(S[2 * kt + 1][2] - __bfloat162float(h.x),
                                                       S[2 * kt + 1][3] - __bfloat162float(h.y)));
            }
#pragma unroll
            for (int j = 0; j < 8; j++) {
                uint32_t vbh[4], vbl[4];
                ldsm4(vbh, vst + bV + j * (16 * AT_VROW) + kt * 32);
                ldsm4(vbl, vst + 10240 + bV + j * (16 * AT_VROW) + kt * 32);
                mma16816(O[2 * j],     ph, vbh + 0);
                mma16816(O[2 * j + 1], ph, vbh + 2);
                mma16816(O[2 * j],     ph, vbl + 0);
                mma16816(O[2 * j + 1], ph, vbl + 2);
                mma16816(O[2 * j],     pl, vbh + 0);
                mma16816(O[2 * j + 1], pl, vbh + 2);
            }
        }
    }

    // ---- epilogue ----
    l0 += __shfl_xor_sync(0xffffffff, l0, 1);
    l0 += __shfl_xor_sync(0xffffffff, l0, 2);
    l1 += __shfl_xor_sync(0xffffffff, l1, 1);
    l1 += __shfl_xor_sync(0xffffffff, l1, 2);
    const float inv0 = 1.0f / l0;
    const float inv1 = 1.0f / l1;

    const int bb = bh >> 4, hh2 = bh & 15;
    const int row0 = qb * 64 + w * 16 + g;
    const size_t base0 = (size_t)(bb * 2048 + row0) * 2048 + hh2 * 128 + lam * 2;
    const size_t base1 = base0 + (size_t)8 * 2048;

#pragma unroll
    for (int nt = 0; nt < 16; nt++) {
        float x0 = O[nt][0] * inv0, x1 = O[nt][1] * inv0;
        __nv_bfloat162 hx = __floats2bfloat162_rn(x0, x1);
        __nv_bfloat162 lx = __floats2bfloat162_rn(x0 - __bfloat162float(hx.x),
                                                  x1 - __bfloat162float(hx.y));
        *(uint32_t*)(g_att_hi + base0 + nt * 8) = bf2_bits(hx);
        *(uint32_t*)(g_att_lo + base0 + nt * 8) = bf2_bits(lx);

        float x2 = O[nt][2] * inv1, x3 = O[nt][3] * inv1;
        hx = __floats2bfloat162_rn(x2, x3);
        lx = __floats2bfloat162_rn(x2 - __bfloat162float(hx.x),
                                   x3 - __bfloat162float(hx.y));
        *(uint32_t*)(g_att_hi + base1 + nt * 8) = bf2_bits(hx);
        *(uint32_t*)(g_att_lo + base1 + nt * 8) = bf2_bits(lx);
    }
}

// ================= launch =================
extern "C" void kernel_launch(void* const* d_in, const int* in_sizes, int n_in,
                              void* d_out, int out_size)
{
    const float* x    = (const float*)d_in[0];
    const float* Wqkv = (const float*)d_in[1];
    const float* bqkv = (const float*)d_in[2];
    const float* Wo   = (const float*)d_in[3];
    const float* bo   = (const float*)d_in[4];
    float* out = (float*)d_out;

    __nv_bfloat16 *xh, *xl, *ah, *al, *wqh, *wql, *woh, *wol;
    cudaGetSymbolAddress((void**)&xh, g_x_hi);
    cudaGetSymbolAddress((void**)&xl, g_x_lo);
    cudaGetSymbolAddress((void**)&ah, g_att_hi);
    cudaGetSymbolAddress((void**)&al, g_att_lo);
    cudaGetSymbolAddress((void**)&wqh, g_WqkvT_hi);
    cudaGetSymbolAddress((void**)&wql, g_WqkvT_lo);
    cudaGetSymbolAddress((void**)&woh, g_WoT_hi);
    cudaGetSymbolAddress((void**)&wol, g_WoT_lo);

    cudaFuncSetAttribute(gemm_tc, cudaFuncAttributeMaxDynamicSharedMemorySize, G_SMEM);
    cudaFuncSetAttribute(gemm_qkv_rope, cudaFuncAttributeMaxDynamicSharedMemorySize, G_SMEM);
    cudaFuncSetAttribute(attn_tc, cudaFuncAttributeMaxDynamicSharedMemorySize, AT_SMEM);

    // prep
    rope_table_kernel<<<(2048 * 64) / 256, 256>>>();
    split_convert<<<(4096 * 2048) / 256, 256>>>(x, xh, xl, 4096 * 2048);
    transpose_split<<<dim3(6144 / 32, 2048 / 32), dim3(32, 8)>>>(Wqkv, wqh, wql, 2048, 6144);
    transpose_split<<<dim3(2048 / 32, 2048 / 32), dim3(32, 8)>>>(Wo, woh, wol, 2048, 2048);

    // 1) QKV projection + fused RoPE/head-split/V-transpose (bf16, proven)
    gemm_qkv_rope<<<dim3(48, 32), 256, G_SMEM>>>(xh, xl, wqh, wql, bqkv);

    // 2) Tensor-core flash attention (64-query CTAs, 2/SM)
    attn_tc<<<dim3(32, 32), 128, AT_SMEM>>>();

    // 3) Output projection
    gemm_tc<<<dim3(16, 32), 256, G_SMEM>>>(ah, al, woh, wol, bo, out, 2048, 2048);
}

// round 12
// speedup vs baseline: 2.5862x; 1.3233x over previous
#include <cuda_runtime.h>
#include <cuda_fp16.h>
#include <cstdint>
#include <math.h>

// ================= scratch =================
__device__ __half g_x_h[4096 * 2048];
__device__ __half g_att_h[4096 * 2048];
__device__ __half g_Wq_h[6144 * 2048];   // 32*WqkvT [n][k]
__device__ __half g_Wq_l[6144 * 2048];
__device__ __half g_Wo_h[2048 * 2048];   // 32*WoT
__device__ __half g_Wo_l[2048 * 2048];
__device__ __half g_qh[4096 * 2048];     // Q hi only (scaled by 1/sqrt(128))
__device__ __half g_kh[4096 * 2048];
__device__ __half g_kl[4096 * 2048];
__device__ __half g_vth[4096 * 2048];    // V^T per head [bh][d][s]
__device__ __half g_vtl[4096 * 2048];
__device__ float2 g_rope[2048 * 64];

// ================= helpers =================
__device__ __forceinline__ uint32_t smem_u32(const void* p) {
    uint32_t a;
    asm("{ .reg .u64 t; cvta.to.shared.u64 t, %1; cvt.u32.u64 %0, t; }" : "=r"(a) : "l"(p));
    return a;
}
__device__ __forceinline__ void ldsm4(uint32_t (&r)[4], uint32_t addr) {
    asm volatile("ldmatrix.sync.aligned.m8n8.x4.shared.b16 {%0,%1,%2,%3}, [%4];"
        : "=r"(r[0]), "=r"(r[1]), "=r"(r[2]), "=r"(r[3]) : "r"(addr));
}
__device__ __forceinline__ void mma16816(float* c, const uint32_t* a, const uint32_t* b) {
    asm volatile("mma.sync.aligned.m16n8k16.row.col.f32.f16.f16.f32 "
        "{%0,%1,%2,%3}, {%4,%5,%6,%7}, {%8,%9}, {%0,%1,%2,%3};"
        : "+f"(c[0]), "+f"(c[1]), "+f"(c[2]), "+f"(c[3])
        : "r"(a[0]), "r"(a[1]), "r"(a[2]), "r"(a[3]), "r"(b[0]), "r"(b[1]));
}
__device__ __forceinline__ void cp16(uint32_t sa, const void* g) {
    asm volatile("cp.async.cg.shared.global [%0], [%1], 16;" :: "r"(sa), "l"(g));
}
#define CP_COMMIT() asm volatile("cp.async.commit_group;" ::: "memory")
#define CP_WAIT0()  asm volatile("cp.async.wait_group 0;" ::: "memory")
__device__ __forceinline__ uint32_t h2_bits(__half2 v) {
    return *reinterpret_cast<uint32_t*>(&v);
}
__device__ __forceinline__ void stage_split(__half* hi, __half* lo, int off, float v) {
    __half h = __float2half(v);
    hi[off] = h;
    lo[off] = __float2half(v - __half2float(h));
}

// ================= prep kernels =================
__global__ void convert_h(const float* __restrict__ in, __half* __restrict__ hi, int n) {
    int i = blockIdx.x * blockDim.x + threadIdx.x;
    if (i < n) hi[i] = __float2half(in[i]);
}

__global__ void rope_table_kernel()
{
    const int idx = blockIdx.x * blockDim.x + threadIdx.x;
    const int j = idx & 63;
    const int s = idx >> 6;
    const float theta = 1.0f / powf(10000.0f, (float)(2 * j) / 128.0f);
    float sn, cs;
    sincosf((float)s * theta, &sn, &cs);
    g_rope[idx] = make_float2(cs, sn);
}

// W[K,N] -> (32*W)^T [N,K] fp16 hi/lo  (prescale keeps lo out of subnormal range)
__global__ void transpose_split_scaled(const float* __restrict__ W,
                                       __half* __restrict__ Thi, __half* __restrict__ Tlo,
                                       int K, int N) {
    __shared__ float s[32][33];
    int n0 = blockIdx.x * 32, k0 = blockIdx.y * 32;
    int tx = threadIdx.x, ty = threadIdx.y;
#pragma unroll
    for (int j = 0; j < 32; j += 8)
        s[ty + j][tx] = W[(size_t)(k0 + ty + j) * N + n0 + tx];
    __syncthreads();
#pragma unroll
    for (int j = 0; j < 32; j += 8) {
        float v = s[tx][ty + j] * 32.0f;
        __half h = __float2half(v);
        size_t o = (size_t)(n0 + ty + j) * K + k0 + tx;
        Thi[o] = h;
        Tlo[o] = __float2half(v - __half2float(h));
    }
}

// ================= GEMM mainloop: C = A(h) @ (Bh+Bl), 2-term fp16 =================
#define STG_A   0
#define STG_B   10240
#define STG_BL  20480
#define STG_BYTES 30720
#define G_SMEM  65536   // mainloop uses 2*30720; epilogue restages 64KB

__device__ __forceinline__ void gemm_cp_chunk(
    uint32_t st,
    const __half* __restrict__ Ah,
    const __half* __restrict__ Bh, const __half* __restrict__ Bl,
    int bm, int bn, int K, int kc, int tid)
{
#pragma unroll
    for (int t = 0; t < 2; t++) {
        const int i = tid + t * 256;
        const int r = i >> 2, c = (i & 3) * 8;
        const uint32_t o = (uint32_t)(r * 80 + (i & 3) * 16);
        cp16(st + STG_A  + o, Ah + (size_t)(bm + r) * K + kc + c);
        cp16(st + STG_B  + o, Bh + (size_t)(bn + r) * K + kc + c);
        cp16(st + STG_BL + o, Bl + (size_t)(bn + r) * K + kc + c);
    }
}

#define GEMM_MAINLOOP(Ah, Bh, Bl, K)                                                \
    float acc[4][4][4];                                                             \
    _Pragma("unroll") for (int i = 0; i < 4; i++)                                   \
    _Pragma("unroll") for (int j = 0; j < 4; j++)                                   \
    _Pragma("unroll") for (int k = 0; k < 4; k++) acc[i][j][k] = 0.0f;              \
    const uint32_t sb0 = smem_u32(smem);                                            \
    const uint32_t aOff = (uint32_t)((wm * 64 + (lane & 15)) * 80 + ((lane >> 4) << 4)); \
    const uint32_t bOff = (uint32_t)((wn * 32 + (lane & 7) + ((lane >> 4) << 3)) * 80    \
                                     + (((lane >> 3) & 1) << 4));                   \
    const int nch = (K) / 32;                                                       \
    gemm_cp_chunk(sb0, Ah, Bh, Bl, bm, bn, K, 0, tid);                              \
    CP_COMMIT();                                                                    \
    for (int c = 0; c < nch; c++) {                                                 \
        CP_WAIT0();                                                                 \
        __syncthreads();                                                            \
        if (c + 1 < nch) {                                                          \
            gemm_cp_chunk(sb0 + (uint32_t)(((c + 1) & 1) * STG_BYTES),              \
                          Ah, Bh, Bl, bm, bn, K, (c + 1) * 32, tid);                \
            CP_COMMIT();                                                            \
        }                                                                           \
        const uint32_t sb = sb0 + (uint32_t)((c & 1) * STG_BYTES);                  \
        _Pragma("unroll")                                                           \
        for (int ks = 0; ks < 2; ks++) {                                            \
            const uint32_t ko = (uint32_t)(ks * 32);                                \
            uint32_t a0[4][4], b0[2][4], b1[2][4];                                  \
            _Pragma("unroll") for (int mi = 0; mi < 4; mi++)                        \
                ldsm4(a0[mi], sb + STG_A + aOff + mi * 1280 + ko);                  \
            _Pragma("unroll") for (int nj = 0; nj < 2; nj++)                        \
                ldsm4(b0[nj], sb + STG_B + bOff + nj * 1280 + ko);                  \
            _Pragma("unroll") for (int nj = 0; nj < 2; nj++)                        \
                ldsm4(b1[nj], sb + STG_BL + bOff + nj * 1280 + ko);                 \
            _Pragma("unroll") for (int mi = 0; mi < 4; mi++)                        \
            _Pragma("unroll") for (int ni = 0; ni < 4; ni++)                        \
                mma16816(acc[mi][ni], a0[mi], &b0[ni >> 1][(ni & 1) * 2]);          \
            _Pragma("unroll") for (int mi = 0; mi < 4; mi++)                        \
            _Pragma("unroll") for (int ni = 0; ni < 4; ni++)                        \
                mma16816(acc[mi][ni], a0[mi], &b1[ni >> 1][(ni & 1) * 2]);          \
        }                                                                           \
    }

// ================= GEMM #2: out-proj (acc/32 + bias) =================
__global__ __launch_bounds__(256, 2) void gemm_tc(
    const __half* __restrict__ Ah,
    const __half* __restrict__ Bh, const __half* __restrict__ Bl,
    const float* __restrict__ bias, float* __restrict__ C, int N, int K)
{
    extern __shared__ char smem[];
    const int tid = threadIdx.x;
    const int lane = tid & 31;
    const int wid = tid >> 5;
    const int wm = wid & 1;
    const int wn = wid >> 1;
    const int bm = blockIdx.y * 128;
    const int bn = blockIdx.x * 128;

    GEMM_MAINLOOP(Ah, Bh, Bl, K)

    const float inv32 = 0.03125f;
    const int rbase = bm + wm * 64 + (lane >> 2);
    const int cbase = bn + wn * 32 + (lane & 3) * 2;
#pragma unroll
    for (int mi = 0; mi < 4; mi++) {
#pragma unroll
        for (int ni = 0; ni < 4; ni++) {
            const int col = cbase + ni * 8;
            const float2 bv = *(const float2*)(bias + col);
            const int r0 = rbase + mi * 16;
            float2 o0, o1;
            o0.x = acc[mi][ni][0] * inv32 + bv.x; o0.y = acc[mi][ni][1] * inv32 + bv.y;
            o1.x = acc[mi][ni][2] * inv32 + bv.x; o1.y = acc[mi][ni][3] * inv32 + bv.y;
            *(float2*)(C + (size_t)r0 * N + col) = o0;
            *(float2*)(C + (size_t)(r0 + 8) * N + col) = o1;
        }
    }
}

// ================= GEMM #1: QKV projection + fused RoPE (table) =================
__global__ __launch_bounds__(256, 2) void gemm_qkv_rope(
    const __half* __restrict__ Ah,
    const __half* __restrict__ Bh, const __half* __restrict__ Bl,
    const float* __restrict__ bias)
{
    extern __shared__ char smem[];
    const int tid = threadIdx.x;
    const int lane = tid & 31;
    const int wid = tid >> 5;
    const int wm = wid & 1;
    const int wn = wid >> 1;
    const int bm = blockIdx.y * 128;
    const int bn = blockIdx.x * 128;
    const int K = 2048;

    GEMM_MAINLOOP(Ah, Bh, Bl, K)

    __syncthreads();

    const float inv32 = 0.03125f;
    const int seg   = bn >> 11;          // 0=Q 1=K 2=V
    const int head  = (bn & 2047) >> 7;
    const int bidx  = bm >> 11;
    const int s_base = bm & 2047;
    const int bhh   = bidx * 16 + head;

    __half* sh_hi = (__half*)smem;            // 128x128 fp16 = 32 KB
    __half* sh_lo = (__half*)(smem + 32768);

    const int rl = wm * 64 + (lane >> 2);
    const int cb = wn * 32 + (lane & 3) * 2;
    const float qscale = 0.08838834764831845f;

#pragma unroll
    for (int mi = 0; mi < 4; mi++) {
#pragma unroll
        for (int ni = 0; ni < 4; ni++) {
            const int c = cb + ni * 8;
            const float b0 = bias[bn + c], b1 = bias[bn + c + 1];
            float v0 = acc[mi][ni][0] * inv32 + b0, v1 = acc[mi][ni][1] * inv32 + b1;
            float w0 = acc[mi][ni][2] * inv32 + b0, w1 = acc[mi][ni][3] * inv32 + b1;
            const int r0 = rl + mi * 16, r1 = r0 + 8;
            if (seg == 0) {
                const int j = c >> 1;
                const float2 t0 = g_rope[(s_base + r0) * 64 + j];
                const float2 t1 = g_rope[(s_base + r1) * 64 + j];
                sh_hi[r0 * 128 + j]      = __float2half((v0 * t0.x - v1 * t0.y) * qscale);
                sh_hi[r0 * 128 + j + 64] = __float2half((v0 * t0.y + v1 * t0.x) * qscale);
                sh_hi[r1 * 128 + j]      = __float2half((w0 * t1.x - w1 * t1.y) * qscale);
                sh_hi[r1 * 128 + j + 64] = __float2half((w0 * t1.y + w1 * t1.x) * qscale);
            } else if (seg == 1) {
                const int j = c >> 1;
                const float2 t0 = g_rope[(s_base + r0) * 64 + j];
                const float2 t1 = g_rope[(s_base + r1) * 64 + j];
                stage_split(sh_hi, sh_lo, r0 * 128 + j,      v0 * t0.x - v1 * t0.y);
                stage_split(sh_hi, sh_lo, r0 * 128 + j + 64, v0 * t0.y + v1 * t0.x);
                stage_split(sh_hi, sh_lo, r1 * 128 + j,      w0 * t1.x - w1 * t1.y);
                stage_split(sh_hi, sh_lo, r1 * 128 + j + 64, w0 * t1.y + w1 * t1.x);
            } else {
                stage_split(sh_hi, sh_lo, c * 128 + r0,       v0);
                stage_split(sh_hi, sh_lo, (c + 1) * 128 + r0, v1);
                stage_split(sh_hi, sh_lo, c * 128 + r1,       w0);
                stage_split(sh_hi, sh_lo, (c + 1) * 128 + r1, w1);
            }
        }
    }
    __syncthreads();

    if (seg == 0) {
        for (int i = tid; i < 2048; i += 256) {
            const int row = i >> 4, q = i & 15;
            const size_t eo = ((size_t)bhh * 2048 + s_base + row) * 128 + q * 8;
            *(uint4*)(g_qh + eo) = *(const uint4*)(sh_hi + row * 128 + q * 8);
        }
    } else if (seg == 1) {
        for (int i = tid; i < 2048; i += 256) {
            const int row = i >> 4, q = i & 15;
            const size_t eo = ((size_t)bhh * 2048 + s_base + row) * 128 + q * 8;
            *(uint4*)(g_kh + eo) = *(const uint4*)(sh_hi + row * 128 + q * 8);
            *(uint4*)(g_kl + eo) = *(const uint4*)(sh_lo + row * 128 + q * 8);
        }
    } else {
        for (int i = tid; i < 2048; i += 256) {
            const int d = i >> 4, q = i & 15;
            const size_t eo = ((size_t)(bhh * 128 + d)) * 2048 + s_base + q * 8;
            *(uint4*)(g_vth + eo) = *(const uint4*)(sh_hi + d * 128 + q * 8);
            *(uint4*)(g_vtl + eo) = *(const uint4*)(sh_lo + d * 128 + q * 8);
        }
    }
}

// ================= flash attention: 2-term fp16, 64 q/CTA, 2 CTAs/SM =================
#define AT_ROW   272
#define AT_VROW  80
#define AT_SMEM  75776

__global__ __launch_bounds__(128) void attn_tc()
{
    extern __shared__ char sm[];
    const uint32_t sb = smem_u32(sm);
    const int tid = threadIdx.x;
    const int lane = tid & 31;
    const int w = tid >> 5;
    const int qb = blockIdx.x;
    const int bh = blockIdx.y;

    const size_t hbase = (size_t)bh * 2048 * 128;
    const uint4* Qh = (const uint4*)(g_qh + hbase + (size_t)qb * 64 * 128);
    const __half* Khp = g_kh + hbase;
    const __half* Klp = g_kl + hbase;
    const __half* Vth = g_vth + (size_t)bh * 128 * 2048;
    const __half* Vtl = g_vtl + (size_t)bh * 128 * 2048;

    // stage Q (64 rows x 16 uint4) into K stage-0 region temporarily
    for (int i = tid; i < 1024; i += 128) {
        const uint32_t off = (uint32_t)((i >> 4) * AT_ROW + (i & 15) * 16);
        *(uint4*)(sm + off) = Qh[i];
    }
    __syncthreads();

    const uint32_t aOff = (uint32_t)((w * 16 + (lane & 15)) * AT_ROW + ((lane >> 4) << 4));
    uint32_t qfh[8][4];
#pragma unroll
    for (int kk = 0; kk < 8; kk++)
        ldsm4(qfh[kk], sb + aOff + kk * 32);
    __syncthreads();

    const uint32_t bOff = (uint32_t)(((lane & 7) + ((lane >> 4) << 3)) * AT_ROW
                                     + (((lane >> 3) & 1) << 4));
    const uint32_t bV   = (uint32_t)(((lane & 7) + ((lane >> 4) << 3)) * AT_VROW
                                     + (((lane >> 3) & 1) << 4));

    float O[16][4];
#pragma unroll
    for (int i = 0; i < 16; i++)
#pragma unroll
        for (int j = 0; j < 4; j++) O[i][j] = 0.0f;
    float m0 = -30000.0f, m1 = -30000.0f, l0 = 0.0f, l1 = 0.0f;
    const int g = lane >> 2, lam = lane & 3;

    auto load_chunk = [&](int kc, int st) {
        const uint32_t kbase = sb + (uint32_t)(st * 17408);
        const uint32_t vbase = sb + 34816u + (uint32_t)(st * 20480);
#pragma unroll
        for (int t = 0; t < 4; t++) {
            const int i = tid + t * 128;
            const int kr = i >> 4, kq = i & 15;
            cp16(kbase + kr * AT_ROW + kq * 16,        Khp + (size_t)(kc + kr) * 128 + kq * 8);
            cp16(kbase + 8704 + kr * AT_ROW + kq * 16, Klp + (size_t)(kc + kr) * 128 + kq * 8);
            const int vr = i >> 2, vq = i & 3;
            cp16(vbase + vr * AT_VROW + vq * 16,         Vth + (size_t)vr * 2048 + kc + vq * 8);
            cp16(vbase + 10240 + vr * AT_VROW + vq * 16, Vtl + (size_t)vr * 2048 + kc + vq * 8);
        }
    };

    load_chunk(0, 0);
    CP_COMMIT();

    for (int cidx = 0; cidx < 64; cidx++) {
        CP_WAIT0();
        __syncthreads();
        if (cidx + 1 < 64) {
            load_chunk((cidx + 1) * 32, (cidx + 1) & 1);
            CP_COMMIT();
        }
        const uint32_t kst = sb + (uint32_t)((cidx & 1) * 17408);
        const uint32_t vst = sb + 34816u + (uint32_t)((cidx & 1) * 20480);

        // ---- S = Q @ K^T (2-term: Qh*Kh + Qh*Kl) ----
        float S[4][4];
#pragma unroll
        for (int t = 0; t < 4; t++)
#pragma unroll
            for (int j = 0; j < 4; j++) S[t][j] = 0.0f;

#pragma unroll
        for (int kk = 0; kk < 8; kk++) {
#pragma unroll
            for (int kg = 0; kg < 2; kg++) {
                uint32_t kbh[4], kbl[4];
                ldsm4(kbh, kst + bOff + kg * (16 * AT_ROW) + kk * 32);
                ldsm4(kbl, kst + 8704 + bOff + kg * (16 * AT_ROW) + kk * 32);
                mma16816(S[2 * kg],     qfh[kk], kbh + 0);
                mma16816(S[2 * kg + 1], qfh[kk], kbh + 2);
                mma16816(S[2 * kg],     qfh[kk], kbl + 0);
                mma16816(S[2 * kg + 1], qfh[kk], kbl + 2);
            }
        }

        // ---- online softmax ----
        float mx0 = -30000.0f, mx1 = -30000.0f;
#pragma unroll
        for (int t = 0; t < 4; t++) {
            mx0 = fmaxf(mx0, fmaxf(S[t][0], S[t][1]));
            mx1 = fmaxf(mx1, fmaxf(S[t][2], S[t][3]));
        }
        mx0 = fmaxf(mx0, __shfl_xor_sync(0xffffffff, mx0, 1));
        mx0 = fmaxf(mx0, __shfl_xor_sync(0xffffffff, mx0, 2));
        mx1 = fmaxf(mx1, __shfl_xor_sync(0xffffffff, mx1, 1));
        mx1 = fmaxf(mx1, __shfl_xor_sync(0xffffffff, mx1, 2));

        const float nm0 = fmaxf(m0, mx0);
        const float nm1 = fmaxf(m1, mx1);
        const float al0 = __expf(fminf(m0 - nm0, 0.0f));
        const float al1 = __expf(fminf(m1 - nm1, 0.0f));
        m0 = nm0; m1 = nm1;

        float s0 = 0.0f, s1 = 0.0f;
#pragma unroll
        for (int t = 0; t < 4; t++) {
            S[t][0] = __expf(fminf(S[t][0] - m0, 0.0f));
            S[t][1] = __expf(fminf(S[t][1] - m0, 0.0f));
            S[t][2] = __expf(fminf(S[t][2] - m1, 0.0f));
            S[t][3] = __expf(fminf(S[t][3] - m1, 0.0f));
            s0 += S[t][0] + S[t][1];
            s1 += S[t][2] + S[t][3];
        }
        l0 = l0 * al0 + s0;
        l1 = l1 * al1 + s1;
#pragma unroll
        for (int nt = 0; nt < 16; nt++) {
            O[nt][0] *= al0; O[nt][1] *= al0;
            O[nt][2] *= al1; O[nt][3] *= al1;
        }

        // ---- O += P @ V (2-term: Ph*Vh + Ph*Vl) ----
#pragma unroll
        for (int kt = 0; kt < 2; kt++) {
            uint32_t ph[4];
            ph[0] = h2_bits(__floats2half2_rn(S[2 * kt][0],     S[2 * kt][1]));
            ph[1] = h2_bits(__floats2half2_rn(S[2 * kt][2],     S[2 * kt][3]));
            ph[2] = h2_bits(__floats2half2_rn(S[2 * kt + 1][0], S[2 * kt + 1][1]));
            ph[3] = h2_bits(__floats2half2_rn(S[2 * kt + 1][2], S[2 * kt + 1][3]));
#pragma unroll
            for (int j = 0; j < 8; j++) {
                uint32_t vbh[4], vbl[4];
                ldsm4(vbh, vst + bV + j * (16 * AT_VROW) + kt * 32);
                ldsm4(vbl, vst + 10240 + bV + j * (16 * AT_VROW) + kt * 32);
                mma16816(O[2 * j],     ph, vbh + 0);
                mma16816(O[2 * j + 1], ph, vbh + 2);
                mma16816(O[2 * j],     ph, vbl + 0);
                mma16816(O[2 * j + 1], ph, vbl + 2);
            }
        }
    }

    // ---- epilogue: att hi only ----
    l0 += __shfl_xor_sync(0xffffffff, l0, 1);
    l0 += __shfl_xor_sync(0xffffffff, l0, 2);
    l1 += __shfl_xor_sync(0xffffffff, l1, 1);
    l1 += __shfl_xor_sync(0xffffffff, l1, 2);
    const float inv0 = 1.0f / l0;
    const float inv1 = 1.0f / l1;

    const int bb = bh >> 4, hh2 = bh & 15;
    const int row0 = qb * 64 + w * 16 + g;
    const size_t base0 = (size_t)(bb * 2048 + row0) * 2048 + hh2 * 128 + lam * 2;
    const size_t base1 = base0 + (size_t)8 * 2048;

#pragma unroll
    for (int nt = 0; nt < 16; nt++) {
        *(uint32_t*)(g_att_h + base0 + nt * 8) =
            h2_bits(__floats2half2_rn(O[nt][0] * inv0, O[nt][1] * inv0));
        *(uint32_t*)(g_att_h + base1 + nt * 8) =
            h2_bits(__floats2half2_rn(O[nt][2] * inv1, O[nt][3] * inv1));
    }
}

// ================= launch =================
extern "C" void kernel_launch(void* const* d_in, const int* in_sizes, int n_in,
                              void* d_out, int out_size)
{
    const float* x    = (const float*)d_in[0];
    const float* Wqkv = (const float*)d_in[1];
    const float* bqkv = (const float*)d_in[2];
    const float* Wo   = (const float*)d_in[3];
    const float* bo   = (const float*)d_in[4];
    float* out = (float*)d_out;

    __half *xh, *ah, *wqh, *wql, *woh, *wol;
    cudaGetSymbolAddress((void**)&xh, g_x_h);
    cudaGetSymbolAddress((void**)&ah, g_att_h);
    cudaGetSymbolAddress((void**)&wqh, g_Wq_h);
    cudaGetSymbolAddress((void**)&wql, g_Wq_l);
    cudaGetSymbolAddress((void**)&woh, g_Wo_h);
    cudaGetSymbolAddress((void**)&wol, g_Wo_l);

    cudaFuncSetAttribute(gemm_tc, cudaFuncAttributeMaxDynamicSharedMemorySize, G_SMEM);
    cudaFuncSetAttribute(gemm_qkv_rope, cudaFuncAttributeMaxDynamicSharedMemorySize, G_SMEM);
    cudaFuncSetAttribute(attn_tc, cudaFuncAttributeMaxDynamicSharedMemorySize, AT_SMEM);

    // prep
    rope_table_kernel<<<(2048 * 64) / 256, 256>>>();
    convert_h<<<(4096 * 2048) / 256, 256>>>(x, xh, 4096 * 2048);
    transpose_split_scaled<<<dim3(6144 / 32, 2048 / 32), dim3(32, 8)>>>(Wqkv, wqh, wql, 2048, 6144);
    transpose_split_scaled<<<dim3(2048 / 32, 2048 / 32), dim3(32, 8)>>>(Wo, woh, wol, 2048, 2048);

    // 1) QKV projection + fused RoPE/head-split/V-transpose
    gemm_qkv_rope<<<dim3(48, 32), 256, G_SMEM>>>(xh, wqh, wql, bqkv);

    // 2) Tensor-core flash attention
    attn_tc<<<dim3(32, 32), 128, AT_SMEM>>>();

    // 3) Output projection
    gemm_tc<<<dim3(16, 32), 256, G_SMEM>>>(ah, woh, wol, bo, out, 2048, 2048);
}

// round 13
// speedup vs baseline: 3.2710x; 1.2648x over previous
#include <cuda_runtime.h>
#include <cuda_fp16.h>
#include <cstdint>
#include <math.h>

// ================= scratch =================
__device__ __half g_x_h[4096 * 2048];
__device__ __half g_att_h[4096 * 2048];
__device__ __half g_Wq_h[6144 * 2048];   // 32*WqkvT [n][k]
__device__ __half g_Wq_l[6144 * 2048];
__device__ __half g_Wo_h[2048 * 2048];   // WoT (unscaled, hi only)
__device__ __half g_qh[4096 * 2048];     // Q hi (1/sqrt(128) folded)
__device__ __half g_kh[4096 * 2048];
__device__ __half g_kl[4096 * 2048];
__device__ __half g_vth[4096 * 2048];    // V^T per head [bh][d][s], hi only
__device__ float2 g_rope[2048 * 64];

// ================= helpers =================
__device__ __forceinline__ uint32_t smem_u32(const void* p) {
    uint32_t a;
    asm("{ .reg .u64 t; cvta.to.shared.u64 t, %1; cvt.u32.u64 %0, t; }" : "=r"(a) : "l"(p));
    return a;
}
__device__ __forceinline__ void ldsm4(uint32_t (&r)[4], uint32_t addr) {
    asm volatile("ldmatrix.sync.aligned.m8n8.x4.shared.b16 {%0,%1,%2,%3}, [%4];"
        : "=r"(r[0]), "=r"(r[1]), "=r"(r[2]), "=r"(r[3]) : "r"(addr));
}
__device__ __forceinline__ void mma16816(float* c, const uint32_t* a, const uint32_t* b) {
    asm volatile("mma.sync.aligned.m16n8k16.row.col.f32.f16.f16.f32 "
        "{%0,%1,%2,%3}, {%4,%5,%6,%7}, {%8,%9}, {%0,%1,%2,%3};"
        : "+f"(c[0]), "+f"(c[1]), "+f"(c[2]), "+f"(c[3])
        : "r"(a[0]), "r"(a[1]), "r"(a[2]), "r"(a[3]), "r"(b[0]), "r"(b[1]));
}
__device__ __forceinline__ void cp16(uint32_t sa, const void* g) {
    asm volatile("cp.async.cg.shared.global [%0], [%1], 16;" :: "r"(sa), "l"(g));
}
#define CP_COMMIT() asm volatile("cp.async.commit_group;" ::: "memory")
#define CP_WAIT0()  asm volatile("cp.async.wait_group 0;" ::: "memory")
__device__ __forceinline__ uint32_t h2_bits(__half2 v) {
    return *reinterpret_cast<uint32_t*>(&v);
}
__device__ __forceinline__ void stage_split(__half* hi, __half* lo, int off, float v) {
    __half h = __float2half(v);
    hi[off] = h;
    lo[off] = __float2half(v - __half2float(h));
}

// ================= prep kernels =================
__global__ void convert_h(const float* __restrict__ in, __half* __restrict__ hi, int n) {
    int i = blockIdx.x * blockDim.x + threadIdx.x;
    if (i < n) hi[i] = __float2half(in[i]);
}

__global__ void rope_table_kernel()
{
    const int idx = blockIdx.x * blockDim.x + threadIdx.x;
    const int j = idx & 63;
    const int s = idx >> 6;
    const float theta = 1.0f / powf(10000.0f, (float)(2 * j) / 128.0f);
    float sn, cs;
    sincosf((float)s * theta, &sn, &cs);
    g_rope[idx] = make_float2(cs, sn);
}

// W[K,N] -> (32*W)^T [N,K] fp16 hi/lo (QKV weights)
__global__ void transpose_split_scaled(const float* __restrict__ W,
                                       __half* __restrict__ Thi, __half* __restrict__ Tlo,
                                       int K, int N) {
    __shared__ float s[32][33];
    int n0 = blockIdx.x * 32, k0 = blockIdx.y * 32;
    int tx = threadIdx.x, ty = threadIdx.y;
#pragma unroll
    for (int j = 0; j < 32; j += 8)
        s[ty + j][tx] = W[(size_t)(k0 + ty + j) * N + n0 + tx];
    __syncthreads();
#pragma unroll
    for (int j = 0; j < 32; j += 8) {
        float v = s[tx][ty + j] * 32.0f;
        __half h = __float2half(v);
        size_t o = (size_t)(n0 + ty + j) * K + k0 + tx;
        Thi[o] = h;
        Tlo[o] = __float2half(v - __half2float(h));
    }
}

// W[K,N] -> W^T [N,K] fp16 hi only (Wo weights)
__global__ void transpose_h(const float* __restrict__ W, __half* __restrict__ Thi,
                            int K, int N) {
    __shared__ float s[32][33];
    int n0 = blockIdx.x * 32, k0 = blockIdx.y * 32;
    int tx = threadIdx.x, ty = threadIdx.y;
#pragma unroll
    for (int j = 0; j < 32; j += 8)
        s[ty + j][tx] = W[(size_t)(k0 + ty + j) * N + n0 + tx];
    __syncthreads();
#pragma unroll
    for (int j = 0; j < 32; j += 8) {
        size_t o = (size_t)(n0 + ty + j) * K + k0 + tx;
        Thi[o] = __float2half(s[tx][ty + j]);
    }
}

// ================= QKV GEMM (2-term B) + fused RoPE epilogue =================
#define STG_A   0
#define STG_B   10240
#define STG_BL  20480
#define STG_BYTES 30720
#define GQ_SMEM  65536   // mainloop 2*30720; epilogue restage 64KB

__device__ __forceinline__ void qkv_cp_chunk(
    uint32_t st, const __half* __restrict__ Ah,
    const __half* __restrict__ Bh, const __half* __restrict__ Bl,
    int bm, int bn, int kc, int tid)
{
#pragma unroll
    for (int t = 0; t < 2; t++) {
        const int i = tid + t * 256;
        const int r = i >> 2, c = (i & 3) * 8;
        const uint32_t o = (uint32_t)(r * 80 + (i & 3) * 16);
        cp16(st + STG_A  + o, Ah + (size_t)(bm + r) * 2048 + kc + c);
        cp16(st + STG_B  + o, Bh + (size_t)(bn + r) * 2048 + kc + c);
        cp16(st + STG_BL + o, Bl + (size_t)(bn + r) * 2048 + kc + c);
    }
}

__global__ __launch_bounds__(256, 2) void gemm_qkv_rope(
    const __half* __restrict__ Ah,
    const __half* __restrict__ Bh, const __half* __restrict__ Bl,
    const float* __restrict__ bias)
{
    extern __shared__ char smem[];
    const int tid = threadIdx.x;
    const int lane = tid & 31;
    const int wid = tid >> 5;
    const int wm = wid & 1;
    const int wn = wid >> 1;
    const int bm = blockIdx.y * 128;
    const int bn = blockIdx.x * 128;

    float acc[4][4][4];
#pragma unroll
    for (int i = 0; i < 4; i++)
#pragma unroll
        for (int j = 0; j < 4; j++)
#pragma unroll
            for (int k = 0; k < 4; k++) acc[i][j][k] = 0.0f;

    const uint32_t sb0 = smem_u32(smem);
    const uint32_t aOff = (uint32_t)((wm * 64 + (lane & 15)) * 80 + ((lane >> 4) << 4));
    const uint32_t bOff = (uint32_t)((wn * 32 + (lane & 7) + ((lane >> 4) << 3)) * 80
                                     + (((lane >> 3) & 1) << 4));

    qkv_cp_chunk(sb0, Ah, Bh, Bl, bm, bn, 0, tid);
    CP_COMMIT();
    for (int c = 0; c < 64; c++) {
        CP_WAIT0();
        __syncthreads();
        if (c + 1 < 64) {
            qkv_cp_chunk(sb0 + (uint32_t)(((c + 1) & 1) * STG_BYTES),
                         Ah, Bh, Bl, bm, bn, (c + 1) * 32, tid);
            CP_COMMIT();
        }
        const uint32_t sb = sb0 + (uint32_t)((c & 1) * STG_BYTES);
#pragma unroll
        for (int ks = 0; ks < 2; ks++) {
            const uint32_t ko = (uint32_t)(ks * 32);
            uint32_t a0[4][4], b0[2][4], b1[2][4];
#pragma unroll
            for (int mi = 0; mi < 4; mi++) ldsm4(a0[mi], sb + STG_A + aOff + mi * 1280 + ko);
#pragma unroll
            for (int nj = 0; nj < 2; nj++) ldsm4(b0[nj], sb + STG_B + bOff + nj * 1280 + ko);
#pragma unroll
            for (int nj = 0; nj < 2; nj++) ldsm4(b1[nj], sb + STG_BL + bOff + nj * 1280 + ko);
#pragma unroll
            for (int mi = 0; mi < 4; mi++)
#pragma unroll
                for (int ni = 0; ni < 4; ni++)
                    mma16816(acc[mi][ni], a0[mi], &b0[ni >> 1][(ni & 1) * 2]);
#pragma unroll
            for (int mi = 0; mi < 4; mi++)
#pragma unroll
                for (int ni = 0; ni < 4; ni++)
                    mma16816(acc[mi][ni], a0[mi], &b1[ni >> 1][(ni & 1) * 2]);
        }
    }

    __syncthreads();

    const float inv32 = 0.03125f;
    const int seg   = bn >> 11;          // 0=Q 1=K 2=V
    const int head  = (bn & 2047) >> 7;
    const int bidx  = bm >> 11;
    const int s_base = bm & 2047;
    const int bhh   = bidx * 16 + head;

    __half* sh_hi = (__half*)smem;
    __half* sh_lo = (__half*)(smem + 32768);

    const int rl = wm * 64 + (lane >> 2);
    const int cb = wn * 32 + (lane & 3) * 2;
    const float qscale = 0.08838834764831845f;

#pragma unroll
    for (int mi = 0; mi < 4; mi++) {
#pragma unroll
        for (int ni = 0; ni < 4; ni++) {
            const int c = cb + ni * 8;
            const float b0 = bias[bn + c], b1 = bias[bn + c + 1];
            float v0 = acc[mi][ni][0] * inv32 + b0, v1 = acc[mi][ni][1] * inv32 + b1;
            float w0 = acc[mi][ni][2] * inv32 + b0, w1 = acc[mi][ni][3] * inv32 + b1;
            const int r0 = rl + mi * 16, r1 = r0 + 8;
            if (seg == 0) {
                const int j = c >> 1;
                const float2 t0 = g_rope[(s_base + r0) * 64 + j];
                const float2 t1 = g_rope[(s_base + r1) * 64 + j];
                sh_hi[r0 * 128 + j]      = __float2half((v0 * t0.x - v1 * t0.y) * qscale);
                sh_hi[r0 * 128 + j + 64] = __float2half((v0 * t0.y + v1 * t0.x) * qscale);
                sh_hi[r1 * 128 + j]      = __float2half((w0 * t1.x - w1 * t1.y) * qscale);
                sh_hi[r1 * 128 + j + 64] = __float2half((w0 * t1.y + w1 * t1.x) * qscale);
            } else if (seg == 1) {
                const int j = c >> 1;
                const float2 t0 = g_rope[(s_base + r0) * 64 + j];
                const float2 t1 = g_rope[(s_base + r1) * 64 + j];
                stage_split(sh_hi, sh_lo, r0 * 128 + j,      v0 * t0.x - v1 * t0.y);
                stage_split(sh_hi, sh_lo, r0 * 128 + j + 64, v0 * t0.y + v1 * t0.x);
                stage_split(sh_hi, sh_lo, r1 * 128 + j,      w0 * t1.x - w1 * t1.y);
                stage_split(sh_hi, sh_lo, r1 * 128 + j + 64, w0 * t1.y + w1 * t1.x);
            } else {
                sh_hi[c * 128 + r0]       = __float2half(v0);
                sh_hi[(c + 1) * 128 + r0] = __float2half(v1);
                sh_hi[c * 128 + r1]       = __float2half(w0);
                sh_hi[(c + 1) * 128 + r1] = __float2half(w1);
            }
        }
    }
    __syncthreads();

    if (seg == 0) {
        for (int i = tid; i < 2048; i += 256) {
            const int row = i >> 4, q = i & 15;
            const size_t eo = ((size_t)bhh * 2048 + s_base + row) * 128 + q * 8;
            *(uint4*)(g_qh + eo) = *(const uint4*)(sh_hi + row * 128 + q * 8);
        }
    } else if (seg == 1) {
        for (int i = tid; i < 2048; i += 256) {
            const int row = i >> 4, q = i & 15;
            const size_t eo = ((size_t)bhh * 2048 + s_base + row) * 128 + q * 8;
            *(uint4*)(g_kh + eo) = *(const uint4*)(sh_hi + row * 128 + q * 8);
            *(uint4*)(g_kl + eo) = *(const uint4*)(sh_lo + row * 128 + q * 8);
        }
    } else {
        for (int i = tid; i < 2048; i += 256) {
            const int d = i >> 4, q = i & 15;
            const size_t eo = ((size_t)(bhh * 128 + d)) * 2048 + s_base + q * 8;
            *(uint4*)(g_vth + eo) = *(const uint4*)(sh_hi + d * 128 + q * 8);
        }
    }
}

// ================= Wo GEMM: pure fp16 1-term =================
#define W1_A 0
#define W1_B 10240
#define W1_STG 20480
#define GW_SMEM (2 * W1_STG)

__global__ __launch_bounds__(256, 2) void gemm_wo(
    const __half* __restrict__ Ah, const __half* __restrict__ Bh,
    const float* __restrict__ bias, float* __restrict__ C)
{
    extern __shared__ char smem[];
    const int tid = threadIdx.x;
    const int lane = tid & 31;
    const int wid = tid >> 5;
    const int wm = wid & 1;
    const int wn = wid >> 1;
    const int bm = blockIdx.y * 128;
    const int bn = blockIdx.x * 128;

    float acc[4][4][4];
#pragma unroll
    for (int i = 0; i < 4; i++)
#pragma unroll
        for (int j = 0; j < 4; j++)
#pragma unroll
            for (int k = 0; k < 4; k++) acc[i][j][k] = 0.0f;

    const uint32_t sb0 = smem_u32(smem);
    const uint32_t aOff = (uint32_t)((wm * 64 + (lane & 15)) * 80 + ((lane >> 4) << 4));
    const uint32_t bOff = (uint32_t)((wn * 32 + (lane & 7) + ((lane >> 4) << 3)) * 80
                                     + (((lane >> 3) & 1) << 4));
    const int r = tid >> 2, cc = (tid & 3) * 8;
    const uint32_t lo = (uint32_t)(r * 80 + (tid & 3) * 16);

    auto load = [&](int kc, int st) {
        const uint32_t base = sb0 + (uint32_t)(st * W1_STG);
        cp16(base + W1_A + lo, Ah + (size_t)(bm + r) * 2048 + kc + cc);
        cp16(base + W1_A + lo + 5120, Ah + (size_t)(bm + r + 64) * 2048 + kc + cc);
        cp16(base + W1_B + lo, Bh + (size_t)(bn + r) * 2048 + kc + cc);
        cp16(base + W1_B + lo + 5120, Bh + (size_t)(bn + r + 64) * 2048 + kc + cc);
    };

    load(0, 0);
    CP_COMMIT();
    for (int c = 0; c < 64; c++) {
        CP_WAIT0();
        __syncthreads();
        if (c + 1 < 64) {
            load((c + 1) * 32, (c + 1) & 1);
            CP_COMMIT();
        }
        const uint32_t sb = sb0 + (uint32_t)((c & 1) * W1_STG);
#pragma unroll
        for (int ks = 0; ks < 2; ks++) {
            const uint32_t ko = (uint32_t)(ks * 32);
            uint32_t a0[4][4], b0[2][4];
#pragma unroll
            for (int mi = 0; mi < 4; mi++) ldsm4(a0[mi], sb + W1_A + aOff + mi * 1280 + ko);
#pragma unroll
            for (int nj = 0; nj < 2; nj++) ldsm4(b0[nj], sb + W1_B + bOff + nj * 1280 + ko);
#pragma unroll
            for (int mi = 0; mi < 4; mi++)
#pragma unroll
                for (int ni = 0; ni < 4; ni++)
                    mma16816(acc[mi][ni], a0[mi], &b0[ni >> 1][(ni & 1) * 2]);
        }
    }

    const int rbase = bm + wm * 64 + (lane >> 2);
    const int cbase = bn + wn * 32 + (lane & 3) * 2;
#pragma unroll
    for (int mi = 0; mi < 4; mi++) {
#pragma unroll
        for (int ni = 0; ni < 4; ni++) {
            const int col = cbase + ni * 8;
            const float2 bv = *(const float2*)(bias + col);
            const int r0 = rbase + mi * 16;
            float2 o0, o1;
            o0.x = acc[mi][ni][0] + bv.x; o0.y = acc[mi][ni][1] + bv.y;
            o1.x = acc[mi][ni][2] + bv.x; o1.y = acc[mi][ni][3] + bv.y;
            *(float2*)(C + (size_t)r0 * 2048 + col) = o0;
            *(float2*)(C + (size_t)(r0 + 8) * 2048 + col) = o1;
        }
    }
}

// ================= flash attention: K 2-term, V 1-term, 3 CTAs/SM =================
// K stage s: s*17408 (hi @0, lo @8704). V stage s: 34816 + s*10240.
#define AT_ROW   272
#define AT_VROW  80
#define AT_SMEM  55296

__global__ __launch_bounds__(128, 3) void attn_tc()
{
    extern __shared__ char sm[];
    const uint32_t sb = smem_u32(sm);
    const int tid = threadIdx.x;
    const int lane = tid & 31;
    const int w = tid >> 5;
    const int qb = blockIdx.x;
    const int bh = blockIdx.y;

    const size_t hbase = (size_t)bh * 2048 * 128;
    const uint4* Qh = (const uint4*)(g_qh + hbase + (size_t)qb * 64 * 128);
    const __half* Khp = g_kh + hbase;
    const __half* Klp = g_kl + hbase;
    const __half* Vth = g_vth + (size_t)bh * 128 * 2048;

    for (int i = tid; i < 1024; i += 128) {
        const uint32_t off = (uint32_t)((i >> 4) * AT_ROW + (i & 15) * 16);
        *(uint4*)(sm + off) = Qh[i];
    }
    __syncthreads();

    const uint32_t aOff = (uint32_t)((w * 16 + (lane & 15)) * AT_ROW + ((lane >> 4) << 4));
    uint32_t qfh[8][4];
#pragma unroll
    for (int kk = 0; kk < 8; kk++)
        ldsm4(qfh[kk], sb + aOff + kk * 32);
    __syncthreads();

    const uint32_t bOff = (uint32_t)(((lane & 7) + ((lane >> 4) << 3)) * AT_ROW
                                     + (((lane >> 3) & 1) << 4));
    const uint32_t bV   = (uint32_t)(((lane & 7) + ((lane >> 4) << 3)) * AT_VROW
                                     + (((lane >> 3) & 1) << 4));

    float O[16][4];
#pragma unroll
    for (int i = 0; i < 16; i++)
#pragma unroll
        for (int j = 0; j < 4; j++) O[i][j] = 0.0f;
    float m0 = -30000.0f, m1 = -30000.0f, l0 = 0.0f, l1 = 0.0f;
    const int g = lane >> 2, lam = lane & 3;

    auto load_chunk = [&](int kc, int st) {
        const uint32_t kbase = sb + (uint32_t)(st * 17408);
        const uint32_t vbase = sb + 34816u + (uint32_t)(st * 10240);
#pragma unroll
        for (int t = 0; t < 4; t++) {
            const int i = tid + t * 128;
            const int kr = i >> 4, kq = i & 15;
            cp16(kbase + kr * AT_ROW + kq * 16,        Khp + (size_t)(kc + kr) * 128 + kq * 8);
            cp16(kbase + 8704 + kr * AT_ROW + kq * 16, Klp + (size_t)(kc + kr) * 128 + kq * 8);
            const int vr = i >> 2, vq = i & 3;
            cp16(vbase + vr * AT_VROW + vq * 16, Vth + (size_t)vr * 2048 + kc + vq * 8);
        }
    };

    load_chunk(0, 0);
    CP_COMMIT();

    for (int cidx = 0; cidx < 64; cidx++) {
        CP_WAIT0();
        __syncthreads();
        if (cidx + 1 < 64) {
            load_chunk((cidx + 1) * 32, (cidx + 1) & 1);
            CP_COMMIT();
        }
        const uint32_t kst = sb + (uint32_t)((cidx & 1) * 17408);
        const uint32_t vst = sb + 34816u + (uint32_t)((cidx & 1) * 10240);

        // ---- S = Qh @ (Kh+Kl)^T ----
        float S[4][4];
#pragma unroll
        for (int t = 0; t < 4; t++)
#pragma unroll
            for (int j = 0; j < 4; j++) S[t][j] = 0.0f;

#pragma unroll
        for (int kk = 0; kk < 8; kk++) {
#pragma unroll
            for (int kg = 0; kg < 2; kg++) {
                uint32_t kbh[4], kbl[4];
                ldsm4(kbh, kst + bOff + kg * (16 * AT_ROW) + kk * 32);
                ldsm4(kbl, kst + 8704 + bOff + kg * (16 * AT_ROW) + kk * 32);
                mma16816(S[2 * kg],     qfh[kk], kbh + 0);
                mma16816(S[2 * kg + 1], qfh[kk], kbh + 2);
                mma16816(S[2 * kg],     qfh[kk], kbl + 0);
                mma16816(S[2 * kg + 1], qfh[kk], kbl + 2);
            }
        }

        // ---- online softmax ----
        float mx0 = -30000.0f, mx1 = -30000.0f;
#pragma unroll
        for (int t = 0; t < 4; t++) {
            mx0 = fmaxf(mx0, fmaxf(S[t][0], S[t][1]));
            mx1 = fmaxf(mx1, fmaxf(S[t][2], S[t][3]));
        }
        mx0 = fmaxf(mx0, __shfl_xor_sync(0xffffffff, mx0, 1));
        mx0 = fmaxf(mx0, __shfl_xor_sync(0xffffffff, mx0, 2));
        mx1 = fmaxf(mx1, __shfl_xor_sync(0xffffffff, mx1, 1));
        mx1 = fmaxf(mx1, __shfl_xor_sync(0xffffffff, mx1, 2));

        const float nm0 = fmaxf(m0, mx0);
        const float nm1 = fmaxf(m1, mx1);
        const float al0 = __expf(fminf(m0 - nm0, 0.0f));
        const float al1 = __expf(fminf(m1 - nm1, 0.0f));
        m0 = nm0; m1 = nm1;

        float s0 = 0.0f, s1 = 0.0f;
#pragma unroll
        for (int t = 0; t < 4; t++) {
            S[t][0] = __expf(fminf(S[t][0] - m0, 0.0f));
            S[t][1] = __expf(fminf(S[t][1] - m0, 0.0f));
            S[t][2] = __expf(fminf(S[t][2] - m1, 0.0f));
            S[t][3] = __expf(fminf(S[t][3] - m1, 0.0f));
            s0 += S[t][0] + S[t][1];
            s1 += S[t][2] + S[t][3];
        }
        l0 = l0 * al0 + s0;
        l1 = l1 * al1 + s1;
#pragma unroll
        for (int nt = 0; nt < 16; nt++) {
            O[nt][0] *= al0; O[nt][1] *= al0;
            O[nt][2] *= al1; O[nt][3] *= al1;
        }

        // ---- O += Ph @ Vh ----
#pragma unroll
        for (int kt = 0; kt < 2; kt++) {
            uint32_t ph[4];
            ph[0] = h2_bits(__floats2half2_rn(S[2 * kt][0],     S[2 * kt][1]));
            ph[1] = h2_bits(__floats2half2_rn(S[2 * kt][2],     S[2 * kt][3]));
            ph[2] = h2_bits(__floats2half2_rn(S[2 * kt + 1][0], S[2 * kt + 1][1]));
            ph[3] = h2_bits(__floats2half2_rn(S[2 * kt + 1][2], S[2 * kt + 1][3]));
#pragma unroll
            for (int j = 0; j < 8; j++) {
                uint32_t vbh[4];
                ldsm4(vbh, vst + bV + j * (16 * AT_VROW) + kt * 32);
                mma16816(O[2 * j],     ph, vbh + 0);
                mma16816(O[2 * j + 1], ph, vbh + 2);
            }
        }
    }

    // ---- epilogue ----
    l0 += __shfl_xor_sync(0xffffffff, l0, 1);
    l0 += __shfl_xor_sync(0xffffffff, l0, 2);
    l1 += __shfl_xor_sync(0xffffffff, l1, 1);
    l1 += __shfl_xor_sync(0xffffffff, l1, 2);
    const float inv0 = 1.0f / l0;
    const float inv1 = 1.0f / l1;

    const int bb = bh >> 4, hh2 = bh & 15;
    const int row0 = qb * 64 + w * 16 + g;
    const size_t base0 = (size_t)(bb * 2048 + row0) * 2048 + hh2 * 128 + lam * 2;
    const size_t base1 = base0 + (size_t)8 * 2048;

#pragma unroll
    for (int nt = 0; nt < 16; nt++) {
        *(uint32_t*)(g_att_h + base0 + nt * 8) =
            h2_bits(__floats2half2_rn(O[nt][0] * inv0, O[nt][1] * inv0));
        *(uint32_t*)(g_att_h + base1 + nt * 8) =
            h2_bits(__floats2half2_rn(O[nt][2] * inv1, O[nt][3] * inv1));
    }
}

// ================= launch =================
extern "C" void kernel_launch(void* const* d_in, const int* in_sizes, int n_in,
                              void* d_out, int out_size)
{
    const float* x    = (const float*)d_in[0];
    const float* Wqkv = (const float*)d_in[1];
    const float* bqkv = (const float*)d_in[2];
    const float* Wo   = (const float*)d_in[3];
    const float* bo   = (const float*)d_in[4];
    float* out = (float*)d_out;

    __half *xh, *ah, *wqh, *wql, *woh;
    cudaGetSymbolAddress((void**)&xh, g_x_h);
    cudaGetSymbolAddress((void**)&ah, g_att_h);
    cudaGetSymbolAddress((void**)&wqh, g_Wq_h);
    cudaGetSymbolAddress((void**)&wql, g_Wq_l);
    cudaGetSymbolAddress((void**)&woh, g_Wo_h);

    cudaFuncSetAttribute(gemm_qkv_rope, cudaFuncAttributeMaxDynamicSharedMemorySize, GQ_SMEM);
    cudaFuncSetAttribute(gemm_wo, cudaFuncAttributeMaxDynamicSharedMemorySize, GW_SMEM);
    cudaFuncSetAttribute(attn_tc, cudaFuncAttributeMaxDynamicSharedMemorySize, AT_SMEM);

    // prep
    rope_table_kernel<<<(2048 * 64) / 256, 256>>>();
    convert_h<<<(4096 * 2048) / 256, 256>>>(x, xh, 4096 * 2048);
    transpose_split_scaled<<<dim3(6144 / 32, 2048 / 32), dim3(32, 8)>>>(Wqkv, wqh, wql, 2048, 6144);
    transpose_h<<<dim3(2048 / 32, 2048 / 32), dim3(32, 8)>>>(Wo, woh, 2048, 2048);

    // 1) QKV projection + fused RoPE/head-split/V-transpose
    gemm_qkv_rope<<<dim3(48, 32), 256, GQ_SMEM>>>(xh, wqh, wql, bqkv);

    // 2) Tensor-core flash attention (K 2-term, V 1-term, 3 CTAs/SM)
    attn_tc<<<dim3(32, 32), 128, AT_SMEM>>>();

    // 3) Output projection (pure fp16)
    gemm_wo<<<dim3(16, 32), 256, GW_SMEM>>>(ah, woh, bo, out);
}

// round 15
// speedup vs baseline: 4.3134x; 1.3187x over previous
#include <cuda_runtime.h>
#include <cuda_fp16.h>
#include <cstdint>
#include <math.h>

// ================= scratch =================
__device__ __half g_x_h[4096 * 2048];
__device__ __half g_att_h[4096 * 2048];
__device__ __half g_Wq_h[6144 * 2048];   // WqkvT [n][k], hi only
__device__ __half g_Wo_h[2048 * 2048];   // WoT, hi only
__device__ __half g_qh[4096 * 2048];     // Q hi (1/sqrt(128) folded)
__device__ __half g_kh[4096 * 2048];
__device__ __half g_kl[4096 * 2048];
__device__ __half g_vth[4096 * 2048];    // V^T per head [bh][d][s], hi only
__device__ float2 g_rope[2048 * 64];

// ================= helpers =================
__device__ __forceinline__ uint32_t smem_u32(const void* p) {
    uint32_t a;
    asm("{ .reg .u64 t; cvta.to.shared.u64 t, %1; cvt.u32.u64 %0, t; }" : "=r"(a) : "l"(p));
    return a;
}
__device__ __forceinline__ void ldsm4(uint32_t (&r)[4], uint32_t addr) {
    asm volatile("ldmatrix.sync.aligned.m8n8.x4.shared.b16 {%0,%1,%2,%3}, [%4];"
        : "=r"(r[0]), "=r"(r[1]), "=r"(r[2]), "=r"(r[3]) : "r"(addr));
}
__device__ __forceinline__ void mma16816(float* c, const uint32_t* a, const uint32_t* b) {
    asm volatile("mma.sync.aligned.m16n8k16.row.col.f32.f16.f16.f32 "
        "{%0,%1,%2,%3}, {%4,%5,%6,%7}, {%8,%9}, {%0,%1,%2,%3};"
        : "+f"(c[0]), "+f"(c[1]), "+f"(c[2]), "+f"(c[3])
        : "r"(a[0]), "r"(a[1]), "r"(a[2]), "r"(a[3]), "r"(b[0]), "r"(b[1]));
}
__device__ __forceinline__ void cp16(uint32_t sa, const void* g) {
    asm volatile("cp.async.cg.shared.global [%0], [%1], 16;" :: "r"(sa), "l"(g));
}
#define CP_COMMIT() asm volatile("cp.async.commit_group;" ::: "memory")
#define CP_WAIT0()  asm volatile("cp.async.wait_group 0;" ::: "memory")
__device__ __forceinline__ uint32_t h2_bits(__half2 v) {
    return *reinterpret_cast<uint32_t*>(&v);
}
__device__ __forceinline__ void stage_split(__half* hi, __half* lo, int off, float v) {
    __half h = __float2half(v);
    hi[off] = h;
    lo[off] = __float2half(v - __half2float(h));
}

// ================= prep kernels =================
__global__ void convert_h(const float* __restrict__ in, __half* __restrict__ hi, int n) {
    int i = blockIdx.x * blockDim.x + threadIdx.x;
    if (i < n) hi[i] = __float2half(in[i]);
}

__global__ void rope_table_kernel()
{
    const int idx = blockIdx.x * blockDim.x + threadIdx.x;
    const int j = idx & 63;
    const int s = idx >> 6;
    const float theta = 1.0f / powf(10000.0f, (float)(2 * j) / 128.0f);
    float sn, cs;
    sincosf((float)s * theta, &sn, &cs);
    g_rope[idx] = make_float2(cs, sn);
}

// W[K,N] -> W^T [N,K] fp16 hi only
__global__ void transpose_h(const float* __restrict__ W, __half* __restrict__ Thi,
                            int K, int N) {
    __shared__ float s[32][33];
    int n0 = blockIdx.x * 32, k0 = blockIdx.y * 32;
    int tx = threadIdx.x, ty = threadIdx.y;
#pragma unroll
    for (int j = 0; j < 32; j += 8)
        s[ty + j][tx] = W[(size_t)(k0 + ty + j) * N + n0 + tx];
    __syncthreads();
#pragma unroll
    for (int j = 0; j < 32; j += 8) {
        size_t o = (size_t)(n0 + ty + j) * K + k0 + tx;
        Thi[o] = __float2half(s[tx][ty + j]);
    }
}

// ================= pure fp16 GEMM mainloop pieces =================
#define W1_A 0
#define W1_B 10240
#define W1_STG 20480
#define GW_SMEM (2 * W1_STG)
#define GQ_SMEM 65536   // qkv epilogue needs 64KB restage

#define FP16_MAINLOOP(Ah, Bh)                                                       \
    float acc[4][4][4];                                                             \
    _Pragma("unroll") for (int i = 0; i < 4; i++)                                   \
    _Pragma("unroll") for (int j = 0; j < 4; j++)                                   \
    _Pragma("unroll") for (int k = 0; k < 4; k++) acc[i][j][k] = 0.0f;              \
    const uint32_t sb0 = smem_u32(smem);                                            \
    const uint32_t aOff = (uint32_t)((wm * 64 + (lane & 15)) * 80 + ((lane >> 4) << 4)); \
    const uint32_t bOff = (uint32_t)((wn * 32 + (lane & 7) + ((lane >> 4) << 3)) * 80    \
                                     + (((lane >> 3) & 1) << 4));                   \
    const int r = tid >> 2, cc = (tid & 3) * 8;                                     \
    const uint32_t lo = (uint32_t)(r * 80 + (tid & 3) * 16);                        \
    auto load = [&](int kc, int st) {                                               \
        const uint32_t base = sb0 + (uint32_t)(st * W1_STG);                        \
        cp16(base + W1_A + lo,        Ah + (size_t)(bm + r) * 2048 + kc + cc);      \
        cp16(base + W1_A + lo + 5120, Ah + (size_t)(bm + r + 64) * 2048 + kc + cc); \
        cp16(base + W1_B + lo,        Bh + (size_t)(bn + r) * 2048 + kc + cc);      \
        cp16(base + W1_B + lo + 5120, Bh + (size_t)(bn + r + 64) * 2048 + kc + cc); \
    };                                                                              \
    load(0, 0);                                                                     \
    CP_COMMIT();                                                                    \
    for (int c = 0; c < 64; c++) {                                                  \
        CP_WAIT0();                                                                 \
        __syncthreads();                                                            \
        if (c + 1 < 64) {                                                           \
            load((c + 1) * 32, (c + 1) & 1);                                        \
            CP_COMMIT();                                                            \
        }                                                                           \
        const uint32_t sb = sb0 + (uint32_t)((c & 1) * W1_STG);                     \
        _Pragma("unroll")                                                           \
        for (int ks = 0; ks < 2; ks++) {                                            \
            const uint32_t ko = (uint32_t)(ks * 32);                                \
            uint32_t a0[4][4], b0[2][4];                                            \
            _Pragma("unroll") for (int mi = 0; mi < 4; mi++)                        \
                ldsm4(a0[mi], sb + W1_A + aOff + mi * 1280 + ko);                   \
            _Pragma("unroll") for (int nj = 0; nj < 2; nj++)                        \
                ldsm4(b0[nj], sb + W1_B + bOff + nj * 1280 + ko);                   \
            _Pragma("unroll") for (int mi = 0; mi < 4; mi++)                        \
            _Pragma("unroll") for (int ni = 0; ni < 4; ni++)                        \
                mma16816(acc[mi][ni], a0[mi], &b0[ni >> 1][(ni & 1) * 2]);          \
        }                                                                           \
    }

// ================= QKV GEMM (1-term fp16) + fused RoPE epilogue =================
__global__ __launch_bounds__(256, 2) void gemm_qkv_rope(
    const __half* __restrict__ Ah, const __half* __restrict__ Bh,
    const float* __restrict__ bias)
{
    extern __shared__ char smem[];
    const int tid = threadIdx.x;
    const int lane = tid & 31;
    const int wid = tid >> 5;
    const int wm = wid & 1;
    const int wn = wid >> 1;
    const int bm = blockIdx.y * 128;
    const int bn = blockIdx.x * 128;

    FP16_MAINLOOP(Ah, Bh)

    __syncthreads();

    const int seg   = bn >> 11;          // 0=Q 1=K 2=V
    const int head  = (bn & 2047) >> 7;
    const int bidx  = bm >> 11;
    const int s_base = bm & 2047;
    const int bhh   = bidx * 16 + head;

    __half* sh_hi = (__half*)smem;
    __half* sh_lo = (__half*)(smem + 32768);

    const int rl = wm * 64 + (lane >> 2);
    const int cb = wn * 32 + (lane & 3) * 2;
    const float qscale = 0.08838834764831845f;

#pragma unroll
    for (int mi = 0; mi < 4; mi++) {
#pragma unroll
        for (int ni = 0; ni < 4; ni++) {
            const int c = cb + ni * 8;
            const float b0 = bias[bn + c], b1 = bias[bn + c + 1];
            float v0 = acc[mi][ni][0] + b0, v1 = acc[mi][ni][1] + b1;
            float w0 = acc[mi][ni][2] + b0, w1 = acc[mi][ni][3] + b1;
            const int r0 = rl + mi * 16, r1 = r0 + 8;
            if (seg == 0) {
                const int j = c >> 1;
                const float2 t0 = g_rope[(s_base + r0) * 64 + j];
                const float2 t1 = g_rope[(s_base + r1) * 64 + j];
                sh_hi[r0 * 128 + j]      = __float2half((v0 * t0.x - v1 * t0.y) * qscale);
                sh_hi[r0 * 128 + j + 64] = __float2half((v0 * t0.y + v1 * t0.x) * qscale);
                sh_hi[r1 * 128 + j]      = __float2half((w0 * t1.x - w1 * t1.y) * qscale);
                sh_hi[r1 * 128 + j + 64] = __float2half((w0 * t1.y + w1 * t1.x) * qscale);
            } else if (seg == 1) {
                const int j = c >> 1;
                const float2 t0 = g_rope[(s_base + r0) * 64 + j];
                const float2 t1 = g_rope[(s_base + r1) * 64 + j];
                stage_split(sh_hi, sh_lo, r0 * 128 + j,      v0 * t0.x - v1 * t0.y);
                stage_split(sh_hi, sh_lo, r0 * 128 + j + 64, v0 * t0.y + v1 * t0.x);
                stage_split(sh_hi, sh_lo, r1 * 128 + j,      w0 * t1.x - w1 * t1.y);
                stage_split(sh_hi, sh_lo, r1 * 128 + j + 64, w0 * t1.y + w1 * t1.x);
            } else {
                sh_hi[c * 128 + r0]       = __float2half(v0);
                sh_hi[(c + 1) * 128 + r0] = __float2half(v1);
                sh_hi[c * 128 + r1]       = __float2half(w0);
                sh_hi[(c + 1) * 128 + r1] = __float2half(w1);
            }
        }
    }
    __syncthreads();

    if (seg == 0) {
        for (int i = tid; i < 2048; i += 256) {
            const int row = i >> 4, q = i & 15;
            const size_t eo = ((size_t)bhh * 2048 + s_base + row) * 128 + q * 8;
            *(uint4*)(g_qh + eo) = *(const uint4*)(sh_hi + row * 128 + q * 8);
        }
    } else if (seg == 1) {
        for (int i = tid; i < 2048; i += 256) {
            const int row = i >> 4, q = i & 15;
            const size_t eo = ((size_t)bhh * 2048 + s_base + row) * 128 + q * 8;
            *(uint4*)(g_kh + eo) = *(const uint4*)(sh_hi + row * 128 + q * 8);
            *(uint4*)(g_kl + eo) = *(const uint4*)(sh_lo + row * 128 + q * 8);
        }
    } else {
        for (int i = tid; i < 2048; i += 256) {
            const int d = i >> 4, q = i & 15;
            const size_t eo = ((size_t)(bhh * 128 + d)) * 2048 + s_base + q * 8;
            *(uint4*)(g_vth + eo) = *(const uint4*)(sh_hi + d * 128 + q * 8);
        }
    }
}

// ================= Wo GEMM: pure fp16 1-term =================
__global__ __launch_bounds__(256, 2) void gemm_wo(
    const __half* __restrict__ Ah, const __half* __restrict__ Bh,
    const float* __restrict__ bias, float* __restrict__ C)
{
    extern __shared__ char smem[];
    const int tid = threadIdx.x;
    const int lane = tid & 31;
    const int wid = tid >> 5;
    const int wm = wid & 1;
    const int wn = wid >> 1;
    const int bm = blockIdx.y * 128;
    const int bn = blockIdx.x * 128;

    FP16_MAINLOOP(Ah, Bh)

    const int rbase = bm + wm * 64 + (lane >> 2);
    const int cbase = bn + wn * 32 + (lane & 3) * 2;
#pragma unroll
    for (int mi = 0; mi < 4; mi++) {
#pragma unroll
        for (int ni = 0; ni < 4; ni++) {
            const int col = cbase + ni * 8;
            const float2 bv = *(const float2*)(bias + col);
            const int r0 = rbase + mi * 16;
            float2 o0, o1;
            o0.x = acc[mi][ni][0] + bv.x; o0.y = acc[mi][ni][1] + bv.y;
            o1.x = acc[mi][ni][2] + bv.x; o1.y = acc[mi][ni][3] + bv.y;
            *(float2*)(C + (size_t)r0 * 2048 + col) = o0;
            *(float2*)(C + (size_t)(r0 + 8) * 2048 + col) = o1;
        }
    }
}

// ================= flash attention: K 2-term, V 1-term, 3 CTAs/SM =================
#define AT_ROW   272
#define AT_VROW  80
#define AT_SMEM  55296

__global__ __launch_bounds__(128, 3) void attn_tc()
{
    extern __shared__ char sm[];
    const uint32_t sb = smem_u32(sm);
    const int tid = threadIdx.x;
    const int lane = tid & 31;
    const int w = tid >> 5;
    const int qb = blockIdx.x;
    const int bh = blockIdx.y;

    const size_t hbase = (size_t)bh * 2048 * 128;
    const uint4* Qh = (const uint4*)(g_qh + hbase + (size_t)qb * 64 * 128);
    const __half* Khp = g_kh + hbase;
    const __half* Klp = g_kl + hbase;
    const __half* Vth = g_vth + (size_t)bh * 128 * 2048;

    for (int i = tid; i < 1024; i += 128) {
        const uint32_t off = (uint32_t)((i >> 4) * AT_ROW + (i & 15) * 16);
        *(uint4*)(sm + off) = Qh[i];
    }
    __syncthreads();

    const uint32_t aOff = (uint32_t)((w * 16 + (lane & 15)) * AT_ROW + ((lane >> 4) << 4));
    uint32_t qfh[8][4];
#pragma unroll
    for (int kk = 0; kk < 8; kk++)
        ldsm4(qfh[kk], sb + aOff + kk * 32);
    __syncthreads();

    const uint32_t bOff = (uint32_t)(((lane & 7) + ((lane >> 4) << 3)) * AT_ROW
                                     + (((lane >> 3) & 1) << 4));
    const uint32_t bV   = (uint32_t)(((lane & 7) + ((lane >> 4) << 3)) * AT_VROW
                                     + (((lane >> 3) & 1) << 4));

    float O[16][4];
#pragma unroll
    for (int i = 0; i < 16; i++)
#pragma unroll
        for (int j = 0; j < 4; j++) O[i][j] = 0.0f;
    float m0 = -30000.0f, m1 = -30000.0f, l0 = 0.0f, l1 = 0.0f;
    const int g = lane >> 2, lam = lane & 3;

    auto load_chunk = [&](int kc, int st) {
        const uint32_t kbase = sb + (uint32_t)(st * 17408);
        const uint32_t vbase = sb + 34816u + (uint32_t)(st * 10240);
#pragma unroll
        for (int t = 0; t < 4; t++) {
            const int i = tid + t * 128;
            const int kr = i >> 4, kq = i & 15;
            cp16(kbase + kr * AT_ROW + kq * 16,        Khp + (size_t)(kc + kr) * 128 + kq * 8);
            cp16(kbase + 8704 + kr * AT_ROW + kq * 16, Klp + (size_t)(kc + kr) * 128 + kq * 8);
            const int vr = i >> 2, vq = i & 3;
            cp16(vbase + vr * AT_VROW + vq * 16, Vth + (size_t)vr * 2048 + kc + vq * 8);
        }
    };

    load_chunk(0, 0);
    CP_COMMIT();

    for (int cidx = 0; cidx < 64; cidx++) {
        CP_WAIT0();
        __syncthreads();
        if (cidx + 1 < 64) {
            load_chunk((cidx + 1) * 32, (cidx + 1) & 1);
            CP_COMMIT();
        }
        const uint32_t kst = sb + (uint32_t)((cidx & 1) * 17408);
        const uint32_t vst = sb + 34816u + (uint32_t)((cidx & 1) * 10240);

        // ---- S = Qh @ (Kh+Kl)^T ----
        float S[4][4];
#pragma unroll
        for (int t = 0; t < 4; t++)
#pragma unroll
            for (int j = 0; j < 4; j++) S[t][j] = 0.0f;

#pragma unroll
        for (int kk = 0; kk < 8; kk++) {
#pragma unroll
            for (int kg = 0; kg < 2; kg++) {
                uint32_t kbh[4], kbl[4];
                ldsm4(kbh, kst + bOff + kg * (16 * AT_ROW) + kk * 32);
                ldsm4(kbl, kst + 8704 + bOff + kg * (16 * AT_ROW) + kk * 32);
                mma16816(S[2 * kg],     qfh[kk], kbh + 0);
                mma16816(S[2 * kg + 1], qfh[kk], kbh + 2);
                mma16816(S[2 * kg],     qfh[kk], kbl + 0);
                mma16816(S[2 * kg + 1], qfh[kk], kbl + 2);
            }
        }

        // ---- online softmax ----
        float mx0 = -30000.0f, mx1 = -30000.0f;
#pragma unroll
        for (int t = 0; t < 4; t++) {
            mx0 = fmaxf(mx0, fmaxf(S[t][0], S[t][1]));
            mx1 = fmaxf(mx1, fmaxf(S[t][2], S[t][3]));
        }
        mx0 = fmaxf(mx0, __shfl_xor_sync(0xffffffff, mx0, 1));
        mx0 = fmaxf(mx0, __shfl_xor_sync(0xffffffff, mx0, 2));
        mx1 = fmaxf(mx1, __shfl_xor_sync(0xffffffff, mx1, 1));
        mx1 = fmaxf(mx1, __shfl_xor_sync(0xffffffff, mx1, 2));

        const float nm0 = fmaxf(m0, mx0);
        const float nm1 = fmaxf(m1, mx1);
        const float al0 = __expf(fminf(m0 - nm0, 0.0f));
        const float al1 = __expf(fminf(m1 - nm1, 0.0f));
        m0 = nm0; m1 = nm1;

        float s0 = 0.0f, s1 = 0.0f;
#pragma unroll
        for (int t = 0; t < 4; t++) {
            S[t][0] = __expf(fminf(S[t][0] - m0, 0.0f));
            S[t][1] = __expf(fminf(S[t][1] - m0, 0.0f));
            S[t][2] = __expf(fminf(S[t][2] - m1, 0.0f));
            S[t][3] = __expf(fminf(S[t][3] - m1, 0.0f));
            s0 += S[t][0] + S[t][1];
            s1 += S[t][2] + S[t][3];
        }
        l0 = l0 * al0 + s0;
        l1 = l1 * al1 + s1;
#pragma unroll
        for (int nt = 0; nt < 16; nt++) {
            O[nt][0] *= al0; O[nt][1] *= al0;
            O[nt][2] *= al1; O[nt][3] *= al1;
        }

        // ---- O += Ph @ Vh ----
#pragma unroll
        for (int kt = 0; kt < 2; kt++) {
            uint32_t ph[4];
            ph[0] = h2_bits(__floats2half2_rn(S[2 * kt][0],     S[2 * kt][1]));
            ph[1] = h2_bits(__floats2half2_rn(S[2 * kt][2],     S[2 * kt][3]));
            ph[2] = h2_bits(__floats2half2_rn(S[2 * kt + 1][0], S[2 * kt + 1][1]));
            ph[3] = h2_bits(__floats2half2_rn(S[2 * kt + 1][2], S[2 * kt + 1][3]));
#pragma unroll
            for (int j = 0; j < 8; j++) {
                uint32_t vbh[4];
                ldsm4(vbh, vst + bV + j * (16 * AT_VROW) + kt * 32);
                mma16816(O[2 * j],     ph, vbh + 0);
                mma16816(O[2 * j + 1], ph, vbh + 2);
            }
        }
    }

    // ---- epilogue ----
    l0 += __shfl_xor_sync(0xffffffff, l0, 1);
    l0 += __shfl_xor_sync(0xffffffff, l0, 2);
    l1 += __shfl_xor_sync(0xffffffff, l1, 1);
    l1 += __shfl_xor_sync(0xffffffff, l1, 2);
    const float inv0 = 1.0f / l0;
    const float inv1 = 1.0f / l1;

    const int bb = bh >> 4, hh2 = bh & 15;
    const int row0 = qb * 64 + w * 16 + g;
    const size_t base0 = (size_t)(bb * 2048 + row0) * 2048 + hh2 * 128 + lam * 2;
    const size_t base1 = base0 + (size_t)8 * 2048;

#pragma unroll
    for (int nt = 0; nt < 16; nt++) {
        *(uint32_t*)(g_att_h + base0 + nt * 8) =
            h2_bits(__floats2half2_rn(O[nt][0] * inv0, O[nt][1] * inv0));
        *(uint32_t*)(g_att_h + base1 + nt * 8) =
            h2_bits(__floats2half2_rn(O[nt][2] * inv1, O[nt][3] * inv1));
    }
}

// ================= launch =================
extern "C" void kernel_launch(void* const* d_in, const int* in_sizes, int n_in,
                              void* d_out, int out_size)
{
    const float* x    = (const float*)d_in[0];
    const float* Wqkv = (const float*)d_in[1];
    const float* bqkv = (const float*)d_in[2];
    const float* Wo   = (const float*)d_in[3];
    const float* bo   = (const float*)d_in[4];
    float* out = (float*)d_out;

    __half *xh, *ah, *wqh, *woh;
    cudaGetSymbolAddress((void**)&xh, g_x_h);
    cudaGetSymbolAddress((void**)&ah, g_att_h);
    cudaGetSymbolAddress((void**)&wqh, g_Wq_h);
    cudaGetSymbolAddress((void**)&woh, g_Wo_h);

    cudaFuncSetAttribute(gemm_qkv_rope, cudaFuncAttributeMaxDynamicSharedMemorySize, GQ_SMEM);
    cudaFuncSetAttribute(gemm_wo, cudaFuncAttributeMaxDynamicSharedMemorySize, GW_SMEM);
    cudaFuncSetAttribute(attn_tc, cudaFuncAttributeMaxDynamicSharedMemorySize, AT_SMEM);

    // prep
    rope_table_kernel<<<(2048 * 64) / 256, 256>>>();
    convert_h<<<(4096 * 2048) / 256, 256>>>(x, xh, 4096 * 2048);
    transpose_h<<<dim3(6144 / 32, 2048 / 32), dim3(32, 8)>>>(Wqkv, wqh, 2048, 6144);
    transpose_h<<<dim3(2048 / 32, 2048 / 32), dim3(32, 8)>>>(Wo, woh, 2048, 2048);

    // 1) QKV projection (pure fp16) + fused RoPE/head-split/V-transpose
    gemm_qkv_rope<<<dim3(48, 32), 256, GQ_SMEM>>>(xh, wqh, bqkv);

    // 2) Tensor-core flash attention (K 2-term, V 1-term)
    attn_tc<<<dim3(32, 32), 128, AT_SMEM>>>();

    // 3) Output projection (pure fp16)
    gemm_wo<<<dim3(16, 32), 256, GW_SMEM>>>(ah, woh, bo, out);
}

// round 16
// speedup vs baseline: 4.7344x; 1.0976x over previous
#include <cuda_runtime.h>
#include <cuda_fp16.h>
#include <cstdint>
#include <math.h>

// ================= scratch =================
__device__ __half g_x_h[4096 * 2048];
__device__ __half g_att_h[4096 * 2048];
__device__ __half g_Wq_h[6144 * 2048];   // WqkvT [n][k], hi only
__device__ __half g_Wo_h[2048 * 2048];   // WoT, hi only
__device__ __half g_qh[4096 * 2048];     // Q hi (1/sqrt(128) folded)
__device__ __half g_kh[4096 * 2048];     // K hi only
__device__ __half g_vth[4096 * 2048];    // V^T per head [bh][d][s], hi only
__device__ float2 g_rope[2048 * 64];

// ================= helpers =================
__device__ __forceinline__ uint32_t smem_u32(const void* p) {
    uint32_t a;
    asm("{ .reg .u64 t; cvta.to.shared.u64 t, %1; cvt.u32.u64 %0, t; }" : "=r"(a) : "l"(p));
    return a;
}
__device__ __forceinline__ void ldsm4(uint32_t (&r)[4], uint32_t addr) {
    asm volatile("ldmatrix.sync.aligned.m8n8.x4.shared.b16 {%0,%1,%2,%3}, [%4];"
        : "=r"(r[0]), "=r"(r[1]), "=r"(r[2]), "=r"(r[3]) : "r"(addr));
}
__device__ __forceinline__ void mma16816(float* c, const uint32_t* a, const uint32_t* b) {
    asm volatile("mma.sync.aligned.m16n8k16.row.col.f32.f16.f16.f32 "
        "{%0,%1,%2,%3}, {%4,%5,%6,%7}, {%8,%9}, {%0,%1,%2,%3};"
        : "+f"(c[0]), "+f"(c[1]), "+f"(c[2]), "+f"(c[3])
        : "r"(a[0]), "r"(a[1]), "r"(a[2]), "r"(a[3]), "r"(b[0]), "r"(b[1]));
}
__device__ __forceinline__ void cp16(uint32_t sa, const void* g) {
    asm volatile("cp.async.cg.shared.global [%0], [%1], 16;" :: "r"(sa), "l"(g));
}
#define CP_COMMIT() asm volatile("cp.async.commit_group;" ::: "memory")
#define CP_WAIT0()  asm volatile("cp.async.wait_group 0;" ::: "memory")
__device__ __forceinline__ uint32_t h2_bits(__half2 v) {
    return *reinterpret_cast<uint32_t*>(&v);
}

// ================= prep kernels =================
__global__ void convert_h(const float* __restrict__ in, __half* __restrict__ hi, int n) {
    int i = blockIdx.x * blockDim.x + threadIdx.x;
    if (i < n) hi[i] = __float2half(in[i]);
}

__global__ void rope_table_kernel()
{
    const int idx = blockIdx.x * blockDim.x + threadIdx.x;
    const int j = idx & 63;
    const int s = idx >> 6;
    const float theta = 1.0f / powf(10000.0f, (float)(2 * j) / 128.0f);
    float sn, cs;
    sincosf((float)s * theta, &sn, &cs);
    g_rope[idx] = make_float2(cs, sn);
}

// W[K,N] -> W^T [N,K] fp16 hi only
__global__ void transpose_h(const float* __restrict__ W, __half* __restrict__ Thi,
                            int K, int N) {
    __shared__ float s[32][33];
    int n0 = blockIdx.x * 32, k0 = blockIdx.y * 32;
    int tx = threadIdx.x, ty = threadIdx.y;
#pragma unroll
    for (int j = 0; j < 32; j += 8)
        s[ty + j][tx] = W[(size_t)(k0 + ty + j) * N + n0 + tx];
    __syncthreads();
#pragma unroll
    for (int j = 0; j < 32; j += 8) {
        size_t o = (size_t)(n0 + ty + j) * K + k0 + tx;
        Thi[o] = __float2half(s[tx][ty + j]);
    }
}

// ================= pure fp16 GEMM mainloop pieces (proven R15) =================
#define W1_A 0
#define W1_B 10240
#define W1_STG 20480
#define GW_SMEM (2 * W1_STG)
#define GQ_SMEM 65536   // qkv epilogue restage

#define FP16_MAINLOOP(Ah, Bh)                                                       \
    float acc[4][4][4];                                                             \
    _Pragma("unroll") for (int i = 0; i < 4; i++)                                   \
    _Pragma("unroll") for (int j = 0; j < 4; j++)                                   \
    _Pragma("unroll") for (int k = 0; k < 4; k++) acc[i][j][k] = 0.0f;              \
    const uint32_t sb0 = smem_u32(smem);                                            \
    const uint32_t aOff = (uint32_t)((wm * 64 + (lane & 15)) * 80 + ((lane >> 4) << 4)); \
    const uint32_t bOff = (uint32_t)((wn * 32 + (lane & 7) + ((lane >> 4) << 3)) * 80    \
                                     + (((lane >> 3) & 1) << 4));                   \
    const int r = tid >> 2, cc = (tid & 3) * 8;                                     \
    const uint32_t lo = (uint32_t)(r * 80 + (tid & 3) * 16);                        \
    auto load = [&](int kc, int st) {                                               \
        const uint32_t base = sb0 + (uint32_t)(st * W1_STG);                        \
        cp16(base + W1_A + lo,        Ah + (size_t)(bm + r) * 2048 + kc + cc);      \
        cp16(base + W1_A + lo + 5120, Ah + (size_t)(bm + r + 64) * 2048 + kc + cc); \
        cp16(base + W1_B + lo,        Bh + (size_t)(bn + r) * 2048 + kc + cc);      \
        cp16(base + W1_B + lo + 5120, Bh + (size_t)(bn + r + 64) * 2048 + kc + cc); \
    };                                                                              \
    load(0, 0);                                                                     \
    CP_COMMIT();                                                                    \
    for (int c = 0; c < 64; c++) {                                                  \
        CP_WAIT0();                                                                 \
        __syncthreads();                                                            \
        if (c + 1 < 64) {                                                           \
            load((c + 1) * 32, (c + 1) & 1);                                        \
            CP_COMMIT();                                                            \
        }                                                                           \
        const uint32_t sb = sb0 + (uint32_t)((c & 1) * W1_STG);                     \
        _Pragma("unroll")                                                           \
        for (int ks = 0; ks < 2; ks++) {                                            \
            const uint32_t ko = (uint32_t)(ks * 32);                                \
            uint32_t a0[4][4], b0[2][4];                                            \
            _Pragma("unroll") for (int mi = 0; mi < 4; mi++)                        \
                ldsm4(a0[mi], sb + W1_A + aOff + mi * 1280 + ko);                   \
            _Pragma("unroll") for (int nj = 0; nj < 2; nj++)                        \
                ldsm4(b0[nj], sb + W1_B + bOff + nj * 1280 + ko);                   \
            _Pragma("unroll") for (int mi = 0; mi < 4; mi++)                        \
            _Pragma("unroll") for (int ni = 0; ni < 4; ni++)                        \
                mma16816(acc[mi][ni], a0[mi], &b0[ni >> 1][(ni & 1) * 2]);          \
        }                                                                           \
    }

// ================= QKV GEMM (1-term fp16) + fused RoPE epilogue =================
__global__ __launch_bounds__(256, 2) void gemm_qkv_rope(
    const __half* __restrict__ Ah, const __half* __restrict__ Bh,
    const float* __restrict__ bias)
{
    extern __shared__ char smem[];
    const int tid = threadIdx.x;
    const int lane = tid & 31;
    const int wid = tid >> 5;
    const int wm = wid & 1;
    const int wn = wid >> 1;
    const int bm = blockIdx.y * 128;
    const int bn = blockIdx.x * 128;

    FP16_MAINLOOP(Ah, Bh)

    __syncthreads();

    const int seg   = bn >> 11;          // 0=Q 1=K 2=V
    const int head  = (bn & 2047) >> 7;
    const int bidx  = bm >> 11;
    const int s_base = bm & 2047;
    const int bhh   = bidx * 16 + head;

    __half* sh_hi = (__half*)smem;

    const int rl = wm * 64 + (lane >> 2);
    const int cb = wn * 32 + (lane & 3) * 2;
    const float qscale = 0.08838834764831845f;

#pragma unroll
    for (int mi = 0; mi < 4; mi++) {
#pragma unroll
        for (int ni = 0; ni < 4; ni++) {
            const int c = cb + ni * 8;
            const float b0 = bias[bn + c], b1 = bias[bn + c + 1];
            float v0 = acc[mi][ni][0] + b0, v1 = acc[mi][ni][1] + b1;
            float w0 = acc[mi][ni][2] + b0, w1 = acc[mi][ni][3] + b1;
            const int r0 = rl + mi * 16, r1 = r0 + 8;
            if (seg < 2) {
                const int j = c >> 1;
                const float sc = (seg == 0) ? qscale : 1.0f;
                const float2 t0 = g_rope[(s_base + r0) * 64 + j];
                const float2 t1 = g_rope[(s_base + r1) * 64 + j];
                sh_hi[r0 * 128 + j]      = __float2half((v0 * t0.x - v1 * t0.y) * sc);
                sh_hi[r0 * 128 + j + 64] = __float2half((v0 * t0.y + v1 * t0.x) * sc);
                sh_hi[r1 * 128 + j]      = __float2half((w0 * t1.x - w1 * t1.y) * sc);
                sh_hi[r1 * 128 + j + 64] = __float2half((w0 * t1.y + w1 * t1.x) * sc);
            } else {
                sh_hi[c * 128 + r0]       = __float2half(v0);
                sh_hi[(c + 1) * 128 + r0] = __float2half(v1);
                sh_hi[c * 128 + r1]       = __float2half(w0);
                sh_hi[(c + 1) * 128 + r1] = __float2half(w1);
            }
        }
    }
    __syncthreads();

    if (seg < 2) {
        __half* Dst = (seg == 0) ? g_qh : g_kh;
        for (int i = tid; i < 2048; i += 256) {
            const int row = i >> 4, q = i & 15;
            const size_t eo = ((size_t)bhh * 2048 + s_base + row) * 128 + q * 8;
            *(uint4*)(Dst + eo) = *(const uint4*)(sh_hi + row * 128 + q * 8);
        }
    } else {
        for (int i = tid; i < 2048; i += 256) {
            const int d = i >> 4, q = i & 15;
            const size_t eo = ((size_t)(bhh * 128 + d)) * 2048 + s_base + q * 8;
            *(uint4*)(g_vth + eo) = *(const uint4*)(sh_hi + d * 128 + q * 8);
        }
    }
}

// ================= Wo GEMM: pure fp16 1-term (proven R15) =================
__global__ __launch_bounds__(256, 2) void gemm_wo(
    const __half* __restrict__ Ah, const __half* __restrict__ Bh,
    const float* __restrict__ bias, float* __restrict__ C)
{
    extern __shared__ char smem[];
    const int tid = threadIdx.x;
    const int lane = tid & 31;
    const int wid = tid >> 5;
    const int wm = wid & 1;
    const int wn = wid >> 1;
    const int bm = blockIdx.y * 128;
    const int bn = blockIdx.x * 128;

    FP16_MAINLOOP(Ah, Bh)

    const int rbase = bm + wm * 64 + (lane >> 2);
    const int cbase = bn + wn * 32 + (lane & 3) * 2;
#pragma unroll
    for (int mi = 0; mi < 4; mi++) {
#pragma unroll
        for (int ni = 0; ni < 4; ni++) {
            const int col = cbase + ni * 8;
            const float2 bv = *(const float2*)(bias + col);
            const int r0 = rbase + mi * 16;
            float2 o0, o1;
            o0.x = acc[mi][ni][0] + bv.x; o0.y = acc[mi][ni][1] + bv.y;
            o1.x = acc[mi][ni][2] + bv.x; o1.y = acc[mi][ni][3] + bv.y;
            *(float2*)(C + (size_t)r0 * 2048 + col) = o0;
            *(float2*)(C + (size_t)(r0 + 8) * 2048 + col) = o1;
        }
    }
}

// ================= flash attention: pure 1-term fp16, 3 CTAs/SM =================
// K stage s: s*8704 (32 rows x 272B). V stage s: 17408 + s*10240 (128 rows x 80B).
#define AT_ROW   272
#define AT_VROW  80
#define AT_SMEM  37888

__global__ __launch_bounds__(128, 3) void attn_tc()
{
    extern __shared__ char sm[];
    const uint32_t sb = smem_u32(sm);
    const int tid = threadIdx.x;
    const int lane = tid & 31;
    const int w = tid >> 5;
    const int qb = blockIdx.x;
    const int bh = blockIdx.y;

    const size_t hbase = (size_t)bh * 2048 * 128;
    const uint4* Qh = (const uint4*)(g_qh + hbase + (size_t)qb * 64 * 128);
    const __half* Khp = g_kh + hbase;
    const __half* Vth = g_vth + (size_t)bh * 128 * 2048;

    // stage Q (64 rows x 272B = 17408 B) across both K stage regions temporarily
    for (int i = tid; i < 1024; i += 128) {
        const uint32_t off = (uint32_t)((i >> 4) * AT_ROW + (i & 15) * 16);
        *(uint4*)(sm + off) = Qh[i];
    }
    __syncthreads();

    const uint32_t aOff = (uint32_t)((w * 16 + (lane & 15)) * AT_ROW + ((lane >> 4) << 4));
    uint32_t qfh[8][4];
#pragma unroll
    for (int kk = 0; kk < 8; kk++)
        ldsm4(qfh[kk], sb + aOff + kk * 32);
    __syncthreads();

    const uint32_t bOff = (uint32_t)(((lane & 7) + ((lane >> 4) << 3)) * AT_ROW
                                     + (((lane >> 3) & 1) << 4));
    const uint32_t bV   = (uint32_t)(((lane & 7) + ((lane >> 4) << 3)) * AT_VROW
                                     + (((lane >> 3) & 1) << 4));

    float O[16][4];
#pragma unroll
    for (int i = 0; i < 16; i++)
#pragma unroll
        for (int j = 0; j < 4; j++) O[i][j] = 0.0f;
    float m0 = -30000.0f, m1 = -30000.0f, l0 = 0.0f, l1 = 0.0f;
    const int g = lane >> 2, lam = lane & 3;

    auto load_chunk = [&](int kc, int st) {
        const uint32_t kbase = sb + (uint32_t)(st * 8704);
        const uint32_t vbase = sb + 17408u + (uint32_t)(st * 10240);
#pragma unroll
        for (int t = 0; t < 4; t++) {
            const int i = tid + t * 128;            // 0..511
            if (t < 4) {
                const int vr = i >> 2, vq = i & 3;  // V: 128 rows x 4 uint4
                cp16(vbase + vr * AT_VROW + vq * 16, Vth + (size_t)vr * 2048 + kc + vq * 8);
            }
            if (t < 4 && i < 512) {
                const int kr = i >> 4, kq = i & 15; // K: 32 rows x 16 uint4
                cp16(kbase + kr * AT_ROW + kq * 16, Khp + (size_t)(kc + kr) * 128 + kq * 8);
            }
        }
    };

    load_chunk(0, 0);
    CP_COMMIT();

    for (int cidx = 0; cidx < 64; cidx++) {
        CP_WAIT0();
        __syncthreads();
        if (cidx + 1 < 64) {
            load_chunk((cidx + 1) * 32, (cidx + 1) & 1);
            CP_COMMIT();
        }
        const uint32_t kst = sb + (uint32_t)((cidx & 1) * 8704);
        const uint32_t vst = sb + 17408u + (uint32_t)((cidx & 1) * 10240);

        // ---- S = Qh @ Kh^T (1-term) ----
        float S[4][4];
#pragma unroll
        for (int t = 0; t < 4; t++)
#pragma unroll
            for (int j = 0; j < 4; j++) S[t][j] = 0.0f;

#pragma unroll
        for (int kk = 0; kk < 8; kk++) {
#pragma unroll
            for (int kg = 0; kg < 2; kg++) {
                uint32_t kbh[4];
                ldsm4(kbh, kst + bOff + kg * (16 * AT_ROW) + kk * 32);
                mma16816(S[2 * kg],     qfh[kk], kbh + 0);
                mma16816(S[2 * kg + 1], qfh[kk], kbh + 2);
            }
        }

        // ---- online softmax ----
        float mx0 = -30000.0f, mx1 = -30000.0f;
#pragma unroll
        for (int t = 0; t < 4; t++) {
            mx0 = fmaxf(mx0, fmaxf(S[t][0], S[t][1]));
            mx1 = fmaxf(mx1, fmaxf(S[t][2], S[t][3]));
        }
        mx0 = fmaxf(mx0, __shfl_xor_sync(0xffffffff, mx0, 1));
        mx0 = fmaxf(mx0, __shfl_xor_sync(0xffffffff, mx0, 2));
        mx1 = fmaxf(mx1, __shfl_xor_sync(0xffffffff, mx1, 1));
        mx1 = fmaxf(mx1, __shfl_xor_sync(0xffffffff, mx1, 2));

        const float nm0 = fmaxf(m0, mx0);
        const float nm1 = fmaxf(m1, mx1);
        const float al0 = __expf(fminf(m0 - nm0, 0.0f));
        const float al1 = __expf(fminf(m1 - nm1, 0.0f));
        m0 = nm0; m1 = nm1;

        float s0 = 0.0f, s1 = 0.0f;
#pragma unroll
        for (int t = 0; t < 4; t++) {
            S[t][0] = __expf(fminf(S[t][0] - m0, 0.0f));
            S[t][1] = __expf(fminf(S[t][1] - m0, 0.0f));
            S[t][2] = __expf(fminf(S[t][2] - m1, 0.0f));
            S[t][3] = __expf(fminf(S[t][3] - m1, 0.0f));
            s0 += S[t][0] + S[t][1];
            s1 += S[t][2] + S[t][3];
        }
        l0 = l0 * al0 + s0;
        l1 = l1 * al1 + s1;
#pragma unroll
        for (int nt = 0; nt < 16; nt++) {
            O[nt][0] *= al0; O[nt][1] *= al0;
            O[nt][2] *= al1; O[nt][3] *= al1;
        }

        // ---- O += Ph @ Vh ----
#pragma unroll
        for (int kt = 0; kt < 2; kt++) {
            uint32_t ph[4];
            ph[0] = h2_bits(__floats2half2_rn(S[2 * kt][0],     S[2 * kt][1]));
            ph[1] = h2_bits(__floats2half2_rn(S[2 * kt][2],     S[2 * kt][3]));
            ph[2] = h2_bits(__floats2half2_rn(S[2 * kt + 1][0], S[2 * kt + 1][1]));
            ph[3] = h2_bits(__floats2half2_rn(S[2 * kt + 1][2], S[2 * kt + 1][3]));
#pragma unroll
            for (int j = 0; j < 8; j++) {
                uint32_t vbh[4];
                ldsm4(vbh, vst + bV + j * (16 * AT_VROW) + kt * 32);
                mma16816(O[2 * j],     ph, vbh + 0);
                mma16816(O[2 * j + 1], ph, vbh + 2);
            }
        }
    }

    // ---- epilogue ----
    l0 += __shfl_xor_sync(0xffffffff, l0, 1);
    l0 += __shfl_xor_sync(0xffffffff, l0, 2);
    l1 += __shfl_xor_sync(0xffffffff, l1, 1);
    l1 += __shfl_xor_sync(0xffffffff, l1, 2);
    const float inv0 = 1.0f / l0;
    const float inv1 = 1.0f / l1;

    const int bb = bh >> 4, hh2 = bh & 15;
    const int row0 = qb * 64 + w * 16 + g;
    const size_t base0 = (size_t)(bb * 2048 + row0) * 2048 + hh2 * 128 + lam * 2;
    const size_t base1 = base0 + (size_t)8 * 2048;

#pragma unroll
    for (int nt = 0; nt < 16; nt++) {
        *(uint32_t*)(g_att_h + base0 + nt * 8) =
            h2_bits(__floats2half2_rn(O[nt][0] * inv0, O[nt][1] * inv0));
        *(uint32_t*)(g_att_h + base1 + nt * 8) =
            h2_bits(__floats2half2_rn(O[nt][2] * inv1, O[nt][3] * inv1));
    }
}

// ================= launch =================
extern "C" void kernel_launch(void* const* d_in, const int* in_sizes, int n_in,
                              void* d_out, int out_size)
{
    const float* x    = (const float*)d_in[0];
    const float* Wqkv = (const float*)d_in[1];
    const float* bqkv = (const float*)d_in[2];
    const float* Wo   = (const float*)d_in[3];
    const float* bo   = (const float*)d_in[4];
    float* out = (float*)d_out;

    __half *xh, *ah, *wqh, *woh;
    cudaGetSymbolAddress((void**)&xh, g_x_h);
    cudaGetSymbolAddress((void**)&ah, g_att_h);
    cudaGetSymbolAddress((void**)&wqh, g_Wq_h);
    cudaGetSymbolAddress((void**)&woh, g_Wo_h);

    cudaFuncSetAttribute(gemm_qkv_rope, cudaFuncAttributeMaxDynamicSharedMemorySize, GQ_SMEM);
    cudaFuncSetAttribute(gemm_wo, cudaFuncAttributeMaxDynamicSharedMemorySize, GW_SMEM);
    cudaFuncSetAttribute(attn_tc, cudaFuncAttributeMaxDynamicSharedMemorySize, AT_SMEM);

    // prep
    rope_table_kernel<<<(2048 * 64) / 256, 256>>>();
    convert_h<<<(4096 * 2048) / 256, 256>>>(x, xh, 4096 * 2048);
    transpose_h<<<dim3(6144 / 32, 2048 / 32), dim3(32, 8)>>>(Wqkv, wqh, 2048, 6144);
    transpose_h<<<dim3(2048 / 32, 2048 / 32), dim3(32, 8)>>>(Wo, woh, 2048, 2048);

    // 1) QKV projection (pure fp16) + fused RoPE/head-split/V-transpose
    gemm_qkv_rope<<<dim3(48, 32), 256, GQ_SMEM>>>(xh, wqh, bqkv);

    // 2) Tensor-core flash attention (pure 1-term fp16)
    attn_tc<<<dim3(32, 32), 128, AT_SMEM>>>();

    // 3) Output projection (pure fp16)
    gemm_wo<<<dim3(16, 32), 256, GW_SMEM>>>(ah, woh, bo, out);
}